// round 11
// baseline (speedup 1.0000x reference)
#include <cuda_runtime.h>
#include <cuda_bf16.h>
#include <cstdint>
#include <cstddef>

#define NN 100000
#define DD 128
#define AA 3
#define PP 50000
#define EE 500000
#define EFN 500000

#define ND  ((size_t)NN * DD)
#define AND ((size_t)AA * NN * DD)
#define PD  ((size_t)PP * DD)
#define NBLK 98   // (NN + 1023) / 1024

// ---------------- scratch (static device globals; no allocation) ----------------
__device__ float  g_hbuf  [AA * PP * DD];    // compact h rows (population)
__device__ float  g_xatt_b[AA * NN * DD];
__device__ float  g_agg   [4 * NN * DD];     // slots 0-2: attr agg; slot 3: family agg
__device__ float  g_C     [AA * 128 * 128];  // folded proj @ aggW2^T, [o2][i]
__device__ float  g_MT    [AA * 128 * 128];  // (inv(proj)+I)^T: [o][i]
__device__ int    g_ipop  [NN];              // node -> pop position+1 (0 = absent)
// CSR structures for the 7 edge graphs (0-2: attr dst-seg, 3-5: attr src-seg, 6: family)
__device__ int    g_rowptr[7 * (NN + 1)];
__device__ int    g_fill  [7 * NN];
__device__ int    g_eord  [7 * EE];
__device__ int    g_bsum  [7 * NBLK];

// m16n8k16 bf16 mma (sm_80+ portable)
__device__ __forceinline__ void mma16(float* c, const uint32_t* a, uint32_t b0, uint32_t b1) {
    asm volatile("mma.sync.aligned.m16n8k16.row.col.f32.bf16.bf16.f32 "
                 "{%0,%1,%2,%3}, {%4,%5,%6,%7}, {%8,%9}, {%0,%1,%2,%3};"
                 : "+f"(c[0]), "+f"(c[1]), "+f"(c[2]), "+f"(c[3])
                 : "r"(a[0]), "r"(a[1]), "r"(a[2]), "r"(a[3]), "r"(b0), "r"(b1));
}
// split (x,y) into packed bf16x2 hi + lo
__device__ __forceinline__ uint32_t packsplit(float x, float y, uint32_t& lopack) {
    float hx = __bfloat162float(__float2bfloat16(x));
    float hy = __bfloat162float(__float2bfloat16(y));
    uint32_t hi;
    asm("cvt.rn.bf16x2.f32 %0, %1, %2;" : "=r"(hi) : "f"(hy), "f"(hx));
    asm("cvt.rn.bf16x2.f32 %0, %1, %2;" : "=r"(lopack) : "f"(y - hy), "f"(x - hx));
    return hi;
}

// ---------------- fold kernel: C[a][o2][i] = sum_o proj[a][i][o] * aggW[o2][128+o]
__global__ __launch_bounds__(1024)
void foldC(const float* __restrict__ proj, const float* __restrict__ aggW) {
    int a = blockIdx.x;
    for (int idx = threadIdx.x; idx < 16384; idx += 1024) {
        int o2 = idx >> 7, i = idx & 127;
        const float* pr = proj + (size_t)a * 16384 + (size_t)i * 128;
        const float* aw = aggW + (size_t)o2 * 256 + 128;
        float s = 0.0f;
        #pragma unroll 8
        for (int o = 0; o < 128; o++) s = fmaf(pr[o], aw[o], s);
        g_C[(size_t)a * 16384 + idx] = s;
    }
}

// ---------------- ipop: node -> population position + 1 -------------------------
__global__ void ipop_k(const int* __restrict__ pop) {
    int i = blockIdx.x * blockDim.x + threadIdx.x;
    if (i < PP) g_ipop[pop[i]] = i + 1;
}

// ---------------- fp64 in-place Gauss-Jordan inverse, all in SMEM ---------------
__global__ __launch_bounds__(1024)
void inv_kernel(const float* __restrict__ proj) {
    extern __shared__ double S[];            // 128*128
    __shared__ double pv[128];
    __shared__ int    pi[128];
    __shared__ int    perm[128];

    int a = blockIdx.x;
    int tid = threadIdx.x;
    int c = tid & 127, r0 = (tid >> 7) << 4;

    for (int idx = tid; idx < 16384; idx += 1024)
        S[idx] = (double)proj[(size_t)a * 16384 + idx];
    __syncthreads();

    for (int k = 0; k < 128; k++) {
        if (tid < 128) {
            pv[tid] = (tid >= k) ? fabs(S[tid * 128 + k]) : -1.0;
            pi[tid] = tid;
        }
        __syncthreads();
        for (int s = 64; s > 0; s >>= 1) {
            if (tid < s && pv[tid + s] > pv[tid]) { pv[tid] = pv[tid + s]; pi[tid] = pi[tid + s]; }
            __syncthreads();
        }
        int piv = pi[0];
        if (tid == 0) perm[k] = piv;
        if (tid < 128) {
            double vk = S[k * 128 + tid];
            if (piv != k) {
                double vp = S[piv * 128 + tid];
                S[piv * 128 + tid] = vk;
                vk = vp;
            }
            pv[tid] = vk;
        }
        __syncthreads();
        double d = pv[k];
        if (tid < 128) {
            double nv = ((tid == k) ? 1.0 : pv[tid]) / d;
            S[k * 128 + tid] = nv;
            pv[tid] = nv;
        }
        __syncthreads();
        double rk = pv[c];
        double f[16];
        #pragma unroll
        for (int m = 0; m < 16; m++) {
            int r = r0 + m;
            f[m] = (r == k) ? 0.0 : S[r * 128 + k];
        }
        __syncthreads();
        #pragma unroll
        for (int m = 0; m < 16; m++) {
            int r = r0 + m;
            if (r != k) {
                double v = S[r * 128 + c];
                if (c == k) v = 0.0;
                S[r * 128 + c] = v - f[m] * rk;
            }
        }
        __syncthreads();
    }
    for (int k = 127; k >= 0; k--) {
        int p = perm[k];
        if (p != k && tid < 128) {
            double t = S[tid * 128 + k];
            S[tid * 128 + k] = S[tid * 128 + p];
            S[tid * 128 + p] = t;
        }
        __syncthreads();
    }
    for (int idx = tid; idx < 16384; idx += 1024) {
        int o = idx >> 7, i = idx & 127;
        g_MT[(size_t)a * 16384 + idx] = (float)(S[i * 128 + o] + (i == o ? 1.0 : 0.0));
    }
}

// ---------------- CSR build ------------------------------------------------------
__device__ __forceinline__ void graph_ptrs(int g, const int* eia, const int* eif,
                                           const int** gi, const int** si) {
    if (g < 3)      { *gi = eia + (size_t)g * 2 * EE;            *si = eia + (size_t)g * 2 * EE + EE; }
    else if (g < 6) { *gi = eia + (size_t)(g - 3) * 2 * EE + EE; *si = eia + (size_t)(g - 3) * 2 * EE; }
    else            { *gi = eif + EFN;                           *si = eif; }
}

__global__ void hist_k(const int* __restrict__ eia, const int* __restrict__ eif) {
    int g = blockIdx.y;
    const int *gi, *si;
    graph_ptrs(g, eia, eif, &gi, &si);
    int e = blockIdx.x * blockDim.x + threadIdx.x;
    if (e < EE) atomicAdd(g_fill + (size_t)g * NN + si[e], 1);
}

// pass 1: per-block sums
__global__ __launch_bounds__(1024)
void scan_p1() {
    int g = blockIdx.y, b = blockIdx.x, tid = threadIdx.x;
    int i = b * 1024 + tid;
    int v = (i < NN) ? g_fill[(size_t)g * NN + i] : 0;
    #pragma unroll
    for (int o = 16; o; o >>= 1) v += __shfl_down_sync(~0u, v, o);
    __shared__ int w[32];
    if ((tid & 31) == 0) w[tid >> 5] = v;
    __syncthreads();
    if (tid < 32) {
        int x = w[tid];
        #pragma unroll
        for (int o = 16; o; o >>= 1) x += __shfl_down_sync(~0u, x, o);
        if (tid == 0) g_bsum[g * NBLK + b] = x;
    }
}
// pass 2: scan block sums (7 graphs, one lane each)
__global__ void scan_p2() {
    int wid = threadIdx.x >> 5, lane = threadIdx.x & 31;
    if (wid < 7 && lane == 0) {
        int run = 0;
        for (int j = 0; j < NBLK; j++) {
            int t = g_bsum[wid * NBLK + j];
            g_bsum[wid * NBLK + j] = run;
            run += t;
        }
        g_rowptr[(size_t)wid * (NN + 1) + NN] = run;
    }
}
// pass 3: block-local exclusive scan + base; writes rowptr and fill cursors
__global__ __launch_bounds__(1024)
void scan_p3() {
    int g = blockIdx.y, b = blockIdx.x, tid = threadIdx.x;
    int i = b * 1024 + tid;
    int v = (i < NN) ? g_fill[(size_t)g * NN + i] : 0;
    __shared__ int s[1024];
    s[tid] = v;
    __syncthreads();
    for (int off = 1; off < 1024; off <<= 1) {
        int t = (tid >= off) ? s[tid - off] : 0;
        __syncthreads();
        s[tid] += t;
        __syncthreads();
    }
    if (i < NN) {
        int val = g_bsum[g * NBLK + b] + s[tid] - v;
        g_rowptr[(size_t)g * (NN + 1) + i] = val;
        g_fill[(size_t)g * NN + i] = val;
    }
}

__global__ void fill_k(const int* __restrict__ eia, const int* __restrict__ eif) {
    int g = blockIdx.y;
    const int *gi, *si;
    graph_ptrs(g, eia, eif, &gi, &si);
    int e = blockIdx.x * blockDim.x + threadIdx.x;
    if (e < EE) {
        int pos = atomicAdd(g_fill + (size_t)g * NN + si[e], 1);
        g_eord[(size_t)g * EE + pos] = gi[e];
    }
}

// ---------------- gather-mean ----------------------------------------------------
__global__ __launch_bounds__(256)
void gather_mean(const float* __restrict__ data, long dataBStr,
                 int gbase, int fam4, float* __restrict__ outp, long outBStr) {
    int a = blockIdx.y;
    int g = (fam4 && a == 3) ? 6 : (gbase + a);
    const float* d = data + (size_t)a * dataBStr;
    float* o = outp + (size_t)a * outBStr;
    const int* rp = g_rowptr + (size_t)g * (NN + 1);
    const int* eo = g_eord + (size_t)g * EE;

    int node = blockIdx.x * 8 + (threadIdx.x >> 5);
    int lane = threadIdx.x & 31;
    if (node >= NN) return;
    int s = rp[node], e = rp[node + 1];
    float4 acc = make_float4(0.f, 0.f, 0.f, 0.f);
    int j = s;
    for (; j + 1 < e; j += 2) {
        int g0 = eo[j], g1 = eo[j + 1];
        float4 v0 = ((const float4*)(d + (size_t)g0 * DD))[lane];
        float4 v1 = ((const float4*)(d + (size_t)g1 * DD))[lane];
        acc.x += v0.x + v1.x; acc.y += v0.y + v1.y;
        acc.z += v0.z + v1.z; acc.w += v0.w + v1.w;
    }
    if (j < e) {
        float4 v = ((const float4*)(d + (size_t)eo[j] * DD))[lane];
        acc.x += v.x; acc.y += v.y; acc.z += v.z; acc.w += v.w;
    }
    float inv = 1.0f / fmaxf((float)(e - s), 1.0f);
    acc.x *= inv; acc.y *= inv; acc.z *= inv; acc.w *= inv;
    ((float4*)(o + (size_t)node * DD))[lane] = acc;
}

// ---------------- bf16 m16n8k16 fused GEMM, double-buffered ----------------------
// Out[row] = act( In1[row] @ W1^T + In2row @ W2^T + bias )
// GIN: In1 rows (and GOUT: Out rows) indirected via ridx. SEL2: In2 row r taken
// from In2b[sel2[r]-1] when sel2[r]>0 else In2[r]. In2 row pointers live in a
// shared table (sP2) so the mainloop carries no extra registers (R9 profile).
#define RSTR 20
static constexpr int STAGE_WORDS = 128 * RSTR;
static constexpr int GEMM_SMEM = 2048 + 2 * 4 * STAGE_WORDS * 4;   // 83968

template<bool HAS2, bool GIN, bool GOUT, bool RELU, bool HASBIAS, bool SEL2>
__global__ __launch_bounds__(512)
void gemm_tc(const float* __restrict__ In1, int in1Stride, long in1BStr,
             const float* __restrict__ W1, int w1Stride, long w1BStr,
             const float* __restrict__ In2, int in2Stride, long in2BStr,
             const float* __restrict__ In2b, long in2bBStr, const int* __restrict__ sel2,
             const float* __restrict__ W2, int w2Stride, long w2BStr,
             const float* __restrict__ bias, long biasBStr,
             const int*   __restrict__ ridx,
             float* __restrict__ Out, long outBStr, int nrows) {
    extern __shared__ __align__(16) char smem[];
    int*      sRow  = (int*)smem;                            // 512 B
    float*    sBias = (float*)(smem + 512);                  // 512 B
    unsigned long long* sP2 = (unsigned long long*)(smem + 1024);  // 1024 B
    uint32_t* sBase = (uint32_t*)(smem + 2048);

    {
        long a = blockIdx.y;
        In1 += a * in1BStr; W1 += a * w1BStr;
        if (HAS2) { In2 += a * in2BStr; W2 += a * w2BStr; }
        if (SEL2) In2b += a * in2bBStr;
        if (HASBIAS) bias += a * biasBStr;
        Out += a * outBStr;
    }

    int tid = threadIdx.x, wid = tid >> 5, lane = tid & 31;
    int g = lane >> 2, tg = lane & 3;
    int warpM = wid >> 2, warpN = wid & 3;
    int row0 = blockIdx.x * 128;

    if (tid < 128) {
        int gr = row0 + tid;
        int e = 0;
        if (gr < nrows) e = GIN ? ridx[gr] : gr;
        sRow[tid] = e;
        if (HASBIAS) sBias[tid] = bias[tid];
        if (HAS2) {
            int g2 = (gr < nrows) ? gr : (nrows - 1);
            const float* p;
            if (SEL2) {
                int s2 = sel2[g2];
                p = (s2 > 0) ? In2b + (size_t)(s2 - 1) * DD
                             : In2 + (size_t)g2 * in2Stride;
            } else {
                p = In2 + (size_t)g2 * in2Stride;
            }
            sP2[tid] = (unsigned long long)p;
        }
    }
    __syncthreads();

    float acc[2][4][4];
    #pragma unroll
    for (int mt = 0; mt < 2; mt++)
        #pragma unroll
        for (int nt = 0; nt < 4; nt++)
            #pragma unroll
            for (int i = 0; i < 4; i++) acc[mt][nt][i] = 0.0f;

    const int np = HAS2 ? 8 : 4;
    int frr = tid >> 2, fsg = (tid & 3) * 2;

    float4 rA[2], rB[2];

    auto ldg = [&](int p) {
        int op = HAS2 ? (p >> 2) : 0;
        int kc = (p & 3) * 32;
        const float* ap;
        if (op == 0) ap = In1 + (size_t)sRow[frr] * in1Stride;
        else         ap = (const float*)sP2[frr];
        const float* bw = (op == 0) ? W1 : W2;
        int bst = (op == 0) ? w1Stride : w2Stride;
        #pragma unroll
        for (int q = 0; q < 2; q++) {
            int seg = fsg + q;
            rA[q] = *(const float4*)(ap + kc + seg * 4);
            rB[q] = *(const float4*)(bw + (size_t)frr * bst + kc + seg * 4);
        }
    };
    auto sts = [&](int p) {
        uint32_t* st  = sBase + (p & 1) * (4 * STAGE_WORDS);
        uint32_t* tAh = st;
        uint32_t* tAl = st + STAGE_WORDS;
        uint32_t* tBh = st + 2 * STAGE_WORDS;
        uint32_t* tBl = st + 3 * STAGE_WORDS;
        #pragma unroll
        for (int q = 0; q < 2; q++) {
            int seg = fsg + q;
            int wa = frr * RSTR + seg * 2;
            uint32_t lo0, lo1;
            uint32_t hi0 = packsplit(rA[q].x, rA[q].y, lo0);
            uint32_t hi1 = packsplit(rA[q].z, rA[q].w, lo1);
            tAh[wa] = hi0; tAh[wa + 1] = hi1;
            tAl[wa] = lo0; tAl[wa + 1] = lo1;
            uint32_t wl0, wl1;
            uint32_t wh0 = packsplit(rB[q].x, rB[q].y, wl0);
            uint32_t wh1 = packsplit(rB[q].z, rB[q].w, wl1);
            tBh[wa] = wh0; tBh[wa + 1] = wh1;
            tBl[wa] = wl0; tBl[wa + 1] = wl1;
        }
    };

    ldg(0);
    sts(0);
    if (np > 1) ldg(1);
    __syncthreads();

    for (int p = 0; p < np; p++) {
        if (p + 1 < np) sts(p + 1);
        if (p + 2 < np) ldg(p + 2);
        uint32_t* st  = sBase + (p & 1) * (4 * STAGE_WORDS);
        uint32_t* sAhi = st;
        uint32_t* sAlo = st + STAGE_WORDS;
        uint32_t* sBhi = st + 2 * STAGE_WORDS;
        uint32_t* sBlo = st + 3 * STAGE_WORDS;
        #pragma unroll
        for (int ks = 0; ks < 2; ks++) {
            int wb = ks * 8 + tg;
            uint32_t aH[2][4], aL[2][4];
            #pragma unroll
            for (int mt = 0; mt < 2; mt++) {
                int rb = (warpM * 32 + mt * 16 + g) * RSTR;
                aH[mt][0] = sAhi[rb + wb];
                aH[mt][1] = sAhi[rb + 8 * RSTR + wb];
                aH[mt][2] = sAhi[rb + wb + 4];
                aH[mt][3] = sAhi[rb + 8 * RSTR + wb + 4];
                aL[mt][0] = sAlo[rb + wb];
                aL[mt][1] = sAlo[rb + 8 * RSTR + wb];
                aL[mt][2] = sAlo[rb + wb + 4];
                aL[mt][3] = sAlo[rb + 8 * RSTR + wb + 4];
            }
            #pragma unroll
            for (int nt = 0; nt < 4; nt++) {
                int nb = (warpN * 32 + nt * 8 + g) * RSTR;
                uint32_t bh0 = sBhi[nb + wb], bh1 = sBhi[nb + wb + 4];
                uint32_t bl0 = sBlo[nb + wb], bl1 = sBlo[nb + wb + 4];
                #pragma unroll
                for (int mt = 0; mt < 2; mt++) {
                    mma16(acc[mt][nt], aH[mt], bh0, bh1);
                    mma16(acc[mt][nt], aL[mt], bh0, bh1);
                    mma16(acc[mt][nt], aH[mt], bl0, bl1);
                }
            }
        }
        __syncthreads();
    }

    #pragma unroll
    for (int mt = 0; mt < 2; mt++) {
        #pragma unroll
        for (int half = 0; half < 2; half++) {
            int lr = warpM * 32 + mt * 16 + g + half * 8;
            int grow = row0 + lr;
            if (grow < nrows) {
                int orow = GOUT ? sRow[lr] : grow;
                float* ob = Out + (size_t)orow * 128;
                #pragma unroll
                for (int nt = 0; nt < 4; nt++) {
                    int col = warpN * 32 + nt * 8 + tg * 2;
                    float v0 = acc[mt][nt][half * 2 + 0];
                    float v1 = acc[mt][nt][half * 2 + 1];
                    if (HASBIAS) { v0 += sBias[col]; v1 += sBias[col + 1]; }
                    if (RELU) { v0 = fmaxf(v0, 0.0f); v1 = fmaxf(v1, 0.0f); }
                    float2 pp; pp.x = v0; pp.y = v1;
                    *(float2*)(ob + col) = pp;
                }
            }
        }
    }
}

// ---------------- host orchestration -------------------------------------------
extern "C" void kernel_launch(void* const* d_in, const int* in_sizes, int n_in,
                              void* d_out, int out_size) {
    int iXI, iXA, iPF, iPOP, iEIA, iEIF, iPROJ, iAGGW, iAGGB,
        iWL1, iBL1, iWR1, iWL2, iBL2, iWR2, iWL3, iBL3, iWR3;
    if (in_sizes[3] == PP) {  // setup_inputs dict order
        iXI = 0; iXA = 1; iPF = 2; iPOP = 3; iEIA = 4; iEIF = 5;
        iPROJ = 6; iAGGW = 7; iAGGB = 8; iWL1 = 9; iBL1 = 10; iWR1 = 11;
        iWL2 = 12; iBL2 = 13; iWR2 = 14; iWL3 = 15; iBL3 = 16; iWR3 = 17;
    } else {                  // reference() signature order
        iXI = 0; iXA = 1; iPF = 2; iPROJ = 3; iAGGW = 4; iAGGB = 5;
        iWL1 = 6; iBL1 = 7; iWR1 = 8; iWL2 = 9; iBL2 = 10; iWR2 = 11;
        iWL3 = 12; iBL3 = 13; iWR3 = 14; iPOP = 15; iEIA = 16; iEIF = 17;
    }

    const float* xi   = (const float*)d_in[iXI];
    const float* xa   = (const float*)d_in[iXA];
    const float* pf   = (const float*)d_in[iPF];
    const int*   pop  = (const int*)d_in[iPOP];
    const int*   eia  = (const int*)d_in[iEIA];
    const int*   eif  = (const int*)d_in[iEIF];
    const float* proj = (const float*)d_in[iPROJ];
    const float* aggW = (const float*)d_in[iAGGW];
    const float* aggB = (const float*)d_in[iAGGB];
    const float* wl1  = (const float*)d_in[iWL1];
    const float* bl1  = (const float*)d_in[iBL1];
    const float* wr1  = (const float*)d_in[iWR1];
    const float* wl2  = (const float*)d_in[iWL2];
    const float* bl2  = (const float*)d_in[iBL2];
    const float* wr2  = (const float*)d_in[iWR2];
    const float* wl3  = (const float*)d_in[iWL3];
    const float* bl3  = (const float*)d_in[iBL3];
    const float* wr3  = (const float*)d_in[iWR3];

    float* out = (float*)d_out;  // [x_ind_out (N*D)] then [x_att_out (A*N*D)]

    float *hbuf, *xatt_b, *agg, *Cm, *MT;
    int *fillp, *ipop;
    cudaGetSymbolAddress((void**)&hbuf,   g_hbuf);
    cudaGetSymbolAddress((void**)&xatt_b, g_xatt_b);
    cudaGetSymbolAddress((void**)&agg,    g_agg);
    cudaGetSymbolAddress((void**)&Cm,     g_C);
    cudaGetSymbolAddress((void**)&MT,     g_MT);
    cudaGetSymbolAddress((void**)&fillp,  g_fill);
    cudaGetSymbolAddress((void**)&ipop,   g_ipop);
    float* agg3 = agg + 3 * ND;

    cudaFuncSetAttribute(inv_kernel, cudaFuncAttributeMaxDynamicSharedMemorySize, 131072);
    cudaFuncSetAttribute(gemm_tc<true, true, false, true, true, false>,
                         cudaFuncAttributeMaxDynamicSharedMemorySize, GEMM_SMEM);
    cudaFuncSetAttribute(gemm_tc<true, false, false, false, true, true>,
                         cudaFuncAttributeMaxDynamicSharedMemorySize, GEMM_SMEM);
    cudaFuncSetAttribute(gemm_tc<false, true, true, true, false, false>,
                         cudaFuncAttributeMaxDynamicSharedMemorySize, GEMM_SMEM);
    cudaFuncSetAttribute(gemm_tc<true, false, false, false, true, false>,
                         cudaFuncAttributeMaxDynamicSharedMemorySize, GEMM_SMEM);

    const int gP = (PP + 127) / 128;  // 391
    const int gN = (NN + 127) / 128;  // 782
    const int eB = (EE + 255) / 256;
    const int nB = (NN + 7) / 8;

    // --- prep: inverse, fold, ipop ---
    inv_kernel<<<AA, 1024, 131072>>>(proj);
    foldC<<<AA, 1024>>>(proj, aggW);
    cudaMemsetAsync(ipop, 0, (size_t)NN * sizeof(int), 0);
    ipop_k<<<(PP + 255) / 256, 256>>>(pop);

    // --- CSR build for all 7 graphs ---
    cudaMemsetAsync(fillp, 0, (size_t)7 * NN * sizeof(int), 0);
    hist_k<<<dim3(eB, 7), 256>>>(eia, eif);
    scan_p1<<<dim3(NBLK, 7), 1024>>>();
    scan_p2<<<1, 256>>>();
    scan_p3<<<dim3(NBLK, 7), 1024>>>();
    fill_k<<<dim3(eB, 7), 256>>>(eia, eif);

    // 4) hbuf[a][i] = relu(xa[a][pop[i]] @ aggW1^T + pf[i,a,:] @ C[a] + aggB)
    gemm_tc<true, true, false, true, true, false><<<dim3(gP, AA), 512, GEMM_SMEM>>>(
        xa, DD, (long)ND, aggW, 256, 0,
        pf, AA * DD, (long)DD, nullptr, 0, nullptr,
        Cm, 128, 16384,
        aggB, 0, pop,
        hbuf, (long)PD, PP);

    // 5+10) agg = seg-mean of xi: graphs 0-2 (dst-seg) and 6 (family)
    gather_mean<<<dim3(nB, 4), 256>>>(xi, 0, 0, 1, agg, (long)ND);

    // 6) x_att_b = agg @ W_l1^T + b_l1 + x_att_a @ W_r1^T  (x_att_a via hbuf/xa select)
    gemm_tc<true, false, false, false, true, true><<<dim3(gN, AA), 512, GEMM_SMEM>>>(
        agg, DD, (long)ND, wl1, 128, 16384,
        xa, DD, (long)ND, hbuf, (long)PD, ipop,
        wr1, 128, 16384,
        bl1, DD, nullptr,
        xatt_b, (long)ND, NN);

    // 7) population rows: x_att_b[pop] = relu(x_att_b[pop] @ (inv(proj)+I))
    gemm_tc<false, true, true, true, false, false><<<dim3(gP, AA), 512, GEMM_SMEM>>>(
        xatt_b, DD, (long)ND, MT, 128, 16384,
        nullptr, 0, 0, nullptr, 0, nullptr,
        nullptr, 0, 0,
        nullptr, 0, pop,
        xatt_b, (long)ND, PP);

    // 8) agg = seg-mean of x_att_b over src (graphs 3-5)
    gather_mean<<<dim3(nB, AA), 256>>>(xatt_b, (long)ND, 3, 0, agg, (long)ND);

    // 9) x_att_out = agg @ W_l2^T + b_l2 + x_att_b @ W_r2^T  -> d_out[N*D:]
    gemm_tc<true, false, false, false, true, false><<<dim3(gN, AA), 512, GEMM_SMEM>>>(
        agg, DD, (long)ND, wl2, 128, 16384,
        xatt_b, DD, (long)ND, nullptr, 0, nullptr,
        wr2, 128, 16384,
        bl2, DD, nullptr,
        out + ND, (long)ND, NN);

    // 11) x_ind_out = agg3 @ W_l3^T + b_l3 + xi @ W_r3^T -> d_out[0:]
    gemm_tc<true, false, false, false, true, false><<<dim3(gN, 1), 512, GEMM_SMEM>>>(
        agg3, DD, 0, wl3, 128, 0,
        xi, DD, 0, nullptr, 0, nullptr,
        wr3, 128, 0,
        bl3, 0, nullptr,
        out, 0, NN);
}

// round 12
// speedup vs baseline: 1.5034x; 1.5034x over previous
#include <cuda_runtime.h>
#include <cuda_bf16.h>
#include <cstdint>
#include <cstddef>

#define NN 100000
#define DD 128
#define AA 3
#define PP 50000
#define EE 500000
#define EFN 500000

#define ND  ((size_t)NN * DD)
#define AND ((size_t)AA * NN * DD)
#define PD  ((size_t)PP * DD)
#define NBLK 98   // (NN + 1023) / 1024

// ---------------- scratch (static device globals; no allocation) ----------------
__device__ float  g_hbuf  [AA * PP * DD];    // compact h rows (population)
__device__ float  g_xatt_b[AA * NN * DD];
__device__ float  g_agg   [4 * NN * DD];     // slots 0-2: attr agg; slot 3: family agg
__device__ float  g_esf   [AA * PP * DD];
__device__ float  g_projT [AA * 128 * 128];  // proj^T: [o][i]
__device__ float  g_MT    [AA * 128 * 128];  // (inv(proj)+I)^T: [o][i]
__device__ int    g_ipop  [NN];              // node -> pop position+1 (0 = absent)
// CSR structures for the 7 edge graphs (0-2: attr dst-seg, 3-5: attr src-seg, 6: family)
__device__ int    g_rowptr[7 * (NN + 1)];
__device__ int    g_fill  [7 * NN];
__device__ int    g_eord  [7 * EE];
__device__ int    g_bsum  [7 * NBLK];

// m16n8k16 bf16 mma (sm_80+ portable)
__device__ __forceinline__ void mma16(float* c, const uint32_t* a, uint32_t b0, uint32_t b1) {
    asm volatile("mma.sync.aligned.m16n8k16.row.col.f32.bf16.bf16.f32 "
                 "{%0,%1,%2,%3}, {%4,%5,%6,%7}, {%8,%9}, {%0,%1,%2,%3};"
                 : "+f"(c[0]), "+f"(c[1]), "+f"(c[2]), "+f"(c[3])
                 : "r"(a[0]), "r"(a[1]), "r"(a[2]), "r"(a[3]), "r"(b0), "r"(b1));
}
// split (x,y) into packed bf16x2 hi + lo
__device__ __forceinline__ uint32_t packsplit(float x, float y, uint32_t& lopack) {
    float hx = __bfloat162float(__float2bfloat16(x));
    float hy = __bfloat162float(__float2bfloat16(y));
    uint32_t hi;
    asm("cvt.rn.bf16x2.f32 %0, %1, %2;" : "=r"(hi) : "f"(hy), "f"(hx));
    asm("cvt.rn.bf16x2.f32 %0, %1, %2;" : "=r"(lopack) : "f"(y - hy), "f"(x - hx));
    return hi;
}

// ---------------- weight transpose: dst[b][o][i] = src[b][i][o] -----------------
__global__ void transpose_wt(float* __restrict__ dst, const float* __restrict__ src) {
    int b = blockIdx.x;
    const float* s = src + (size_t)b * 16384;
    float* d = dst + (size_t)b * 16384;
    for (int idx = threadIdx.x; idx < 16384; idx += blockDim.x) {
        int o = idx >> 7, i = idx & 127;
        d[idx] = s[(size_t)i * 128 + o];
    }
}

// ---------------- ipop: node -> population position + 1 -------------------------
__global__ void ipop_k(const int* __restrict__ pop) {
    int i = blockIdx.x * blockDim.x + threadIdx.x;
    if (i < PP) g_ipop[pop[i]] = i + 1;
}

// ---------------- fp64 in-place Gauss-Jordan inverse, all in SMEM ---------------
__global__ __launch_bounds__(1024)
void inv_kernel(const float* __restrict__ proj) {
    extern __shared__ double S[];            // 128*128
    __shared__ double pv[128];
    __shared__ int    pi[128];
    __shared__ int    perm[128];

    int a = blockIdx.x;
    int tid = threadIdx.x;
    int c = tid & 127, r0 = (tid >> 7) << 4;

    for (int idx = tid; idx < 16384; idx += 1024)
        S[idx] = (double)proj[(size_t)a * 16384 + idx];
    __syncthreads();

    for (int k = 0; k < 128; k++) {
        if (tid < 128) {
            pv[tid] = (tid >= k) ? fabs(S[tid * 128 + k]) : -1.0;
            pi[tid] = tid;
        }
        __syncthreads();
        for (int s = 64; s > 0; s >>= 1) {
            if (tid < s && pv[tid + s] > pv[tid]) { pv[tid] = pv[tid + s]; pi[tid] = pi[tid + s]; }
            __syncthreads();
        }
        int piv = pi[0];
        if (tid == 0) perm[k] = piv;
        if (tid < 128) {
            double vk = S[k * 128 + tid];
            if (piv != k) {
                double vp = S[piv * 128 + tid];
                S[piv * 128 + tid] = vk;
                vk = vp;
            }
            pv[tid] = vk;
        }
        __syncthreads();
        double d = pv[k];
        if (tid < 128) {
            double nv = ((tid == k) ? 1.0 : pv[tid]) / d;
            S[k * 128 + tid] = nv;
            pv[tid] = nv;
        }
        __syncthreads();
        double rk = pv[c];
        double f[16];
        #pragma unroll
        for (int m = 0; m < 16; m++) {
            int r = r0 + m;
            f[m] = (r == k) ? 0.0 : S[r * 128 + k];
        }
        __syncthreads();
        #pragma unroll
        for (int m = 0; m < 16; m++) {
            int r = r0 + m;
            if (r != k) {
                double v = S[r * 128 + c];
                if (c == k) v = 0.0;
                S[r * 128 + c] = v - f[m] * rk;
            }
        }
        __syncthreads();
    }
    for (int k = 127; k >= 0; k--) {
        int p = perm[k];
        if (p != k && tid < 128) {
            double t = S[tid * 128 + k];
            S[tid * 128 + k] = S[tid * 128 + p];
            S[tid * 128 + p] = t;
        }
        __syncthreads();
    }
    for (int idx = tid; idx < 16384; idx += 1024) {
        int o = idx >> 7, i = idx & 127;
        g_MT[(size_t)a * 16384 + idx] = (float)(S[i * 128 + o] + (i == o ? 1.0 : 0.0));
    }
}

// ---------------- CSR build ------------------------------------------------------
__device__ __forceinline__ void graph_ptrs(int g, const int* eia, const int* eif,
                                           const int** gi, const int** si) {
    if (g < 3)      { *gi = eia + (size_t)g * 2 * EE;            *si = eia + (size_t)g * 2 * EE + EE; }
    else if (g < 6) { *gi = eia + (size_t)(g - 3) * 2 * EE + EE; *si = eia + (size_t)(g - 3) * 2 * EE; }
    else            { *gi = eif + EFN;                           *si = eif; }
}

__global__ void hist_k(const int* __restrict__ eia, const int* __restrict__ eif) {
    int g = blockIdx.y;
    const int *gi, *si;
    graph_ptrs(g, eia, eif, &gi, &si);
    int e = blockIdx.x * blockDim.x + threadIdx.x;
    if (e < EE) atomicAdd(g_fill + (size_t)g * NN + si[e], 1);
}

// pass 1: per-block sums
__global__ __launch_bounds__(1024)
void scan_p1() {
    int g = blockIdx.y, b = blockIdx.x, tid = threadIdx.x;
    int i = b * 1024 + tid;
    int v = (i < NN) ? g_fill[(size_t)g * NN + i] : 0;
    #pragma unroll
    for (int o = 16; o; o >>= 1) v += __shfl_down_sync(~0u, v, o);
    __shared__ int w[32];
    if ((tid & 31) == 0) w[tid >> 5] = v;
    __syncthreads();
    if (tid < 32) {
        int x = w[tid];
        #pragma unroll
        for (int o = 16; o; o >>= 1) x += __shfl_down_sync(~0u, x, o);
        if (tid == 0) g_bsum[g * NBLK + b] = x;
    }
}
// pass 2: scan block sums (7 graphs, one lane each)
__global__ void scan_p2() {
    int wid = threadIdx.x >> 5, lane = threadIdx.x & 31;
    if (wid < 7 && lane == 0) {
        int run = 0;
        for (int j = 0; j < NBLK; j++) {
            int t = g_bsum[wid * NBLK + j];
            g_bsum[wid * NBLK + j] = run;
            run += t;
        }
        g_rowptr[(size_t)wid * (NN + 1) + NN] = run;
    }
}
// pass 3: block-local exclusive scan + base; writes rowptr and fill cursors
__global__ __launch_bounds__(1024)
void scan_p3() {
    int g = blockIdx.y, b = blockIdx.x, tid = threadIdx.x;
    int i = b * 1024 + tid;
    int v = (i < NN) ? g_fill[(size_t)g * NN + i] : 0;
    __shared__ int s[1024];
    s[tid] = v;
    __syncthreads();
    for (int off = 1; off < 1024; off <<= 1) {
        int t = (tid >= off) ? s[tid - off] : 0;
        __syncthreads();
        s[tid] += t;
        __syncthreads();
    }
    if (i < NN) {
        int val = g_bsum[g * NBLK + b] + s[tid] - v;
        g_rowptr[(size_t)g * (NN + 1) + i] = val;
        g_fill[(size_t)g * NN + i] = val;
    }
}

__global__ void fill_k(const int* __restrict__ eia, const int* __restrict__ eif) {
    int g = blockIdx.y;
    const int *gi, *si;
    graph_ptrs(g, eia, eif, &gi, &si);
    int e = blockIdx.x * blockDim.x + threadIdx.x;
    if (e < EE) {
        int pos = atomicAdd(g_fill + (size_t)g * NN + si[e], 1);
        g_eord[(size_t)g * EE + pos] = gi[e];
    }
}

// ---------------- gather-mean ----------------------------------------------------
__global__ __launch_bounds__(256)
void gather_mean(const float* __restrict__ data, long dataBStr,
                 int gbase, int fam4, float* __restrict__ outp, long outBStr) {
    int a = blockIdx.y;
    int g = (fam4 && a == 3) ? 6 : (gbase + a);
    const float* d = data + (size_t)a * dataBStr;
    float* o = outp + (size_t)a * outBStr;
    const int* rp = g_rowptr + (size_t)g * (NN + 1);
    const int* eo = g_eord + (size_t)g * EE;

    int node = blockIdx.x * 8 + (threadIdx.x >> 5);
    int lane = threadIdx.x & 31;
    if (node >= NN) return;
    int s = rp[node], e = rp[node + 1];
    float4 acc = make_float4(0.f, 0.f, 0.f, 0.f);
    int j = s;
    for (; j + 1 < e; j += 2) {
        int g0 = eo[j], g1 = eo[j + 1];
        float4 v0 = ((const float4*)(d + (size_t)g0 * DD))[lane];
        float4 v1 = ((const float4*)(d + (size_t)g1 * DD))[lane];
        acc.x += v0.x + v1.x; acc.y += v0.y + v1.y;
        acc.z += v0.z + v1.z; acc.w += v0.w + v1.w;
    }
    if (j < e) {
        float4 v = ((const float4*)(d + (size_t)eo[j] * DD))[lane];
        acc.x += v.x; acc.y += v.y; acc.z += v.z; acc.w += v.w;
    }
    float inv = 1.0f / fmaxf((float)(e - s), 1.0f);
    acc.x *= inv; acc.y *= inv; acc.z *= inv; acc.w *= inv;
    ((float4*)(o + (size_t)node * DD))[lane] = acc;
}

// ---------------- bf16 m16n8k16 fused GEMM, double-buffered ----------------------
// Out[row] = act( In1[row] @ W1^T + In2row @ W2^T + bias )
// GIN: In1 rows (and GOUT: Out rows) indirected via ridx. SEL2: In2 row r taken
// from In2b[sel2[r]-1] when sel2[r]>0 else In2[r]. In2 row pointers live in a
// shared table (sP2) so the mainloop carries no extra registers.
#define RSTR 20
static constexpr int STAGE_WORDS = 128 * RSTR;
static constexpr int GEMM_SMEM = 2048 + 2 * 4 * STAGE_WORDS * 4;   // 83968

template<bool HAS2, bool GIN, bool GOUT, bool RELU, bool HASBIAS, bool SEL2>
__global__ __launch_bounds__(512)
void gemm_tc(const float* __restrict__ In1, int in1Stride, long in1BStr,
             const float* __restrict__ W1, int w1Stride, long w1BStr,
             const float* __restrict__ In2, int in2Stride, long in2BStr,
             const float* __restrict__ In2b, long in2bBStr, const int* __restrict__ sel2,
             const float* __restrict__ W2, int w2Stride, long w2BStr,
             const float* __restrict__ bias, long biasBStr,
             const int*   __restrict__ ridx,
             float* __restrict__ Out, long outBStr, int nrows) {
    extern __shared__ __align__(16) char smem[];
    int*      sRow  = (int*)smem;                            // 512 B
    float*    sBias = (float*)(smem + 512);                  // 512 B
    unsigned long long* sP2 = (unsigned long long*)(smem + 1024);  // 1024 B
    uint32_t* sBase = (uint32_t*)(smem + 2048);

    {
        long a = blockIdx.y;
        In1 += a * in1BStr; W1 += a * w1BStr;
        if (HAS2) { In2 += a * in2BStr; W2 += a * w2BStr; }
        if (SEL2) In2b += a * in2bBStr;
        if (HASBIAS) bias += a * biasBStr;
        Out += a * outBStr;
    }

    int tid = threadIdx.x, wid = tid >> 5, lane = tid & 31;
    int g = lane >> 2, tg = lane & 3;
    int warpM = wid >> 2, warpN = wid & 3;
    int row0 = blockIdx.x * 128;

    if (tid < 128) {
        int gr = row0 + tid;
        int e = 0;
        if (gr < nrows) e = GIN ? ridx[gr] : gr;
        sRow[tid] = e;
        if (HASBIAS) sBias[tid] = bias[tid];
        if (HAS2) {
            int g2 = (gr < nrows) ? gr : (nrows - 1);
            const float* p;
            if (SEL2) {
                int s2 = sel2[g2];
                p = (s2 > 0) ? In2b + (size_t)(s2 - 1) * DD
                             : In2 + (size_t)g2 * in2Stride;
            } else {
                p = In2 + (size_t)g2 * in2Stride;
            }
            sP2[tid] = (unsigned long long)p;
        }
    }
    __syncthreads();

    float acc[2][4][4];
    #pragma unroll
    for (int mt = 0; mt < 2; mt++)
        #pragma unroll
        for (int nt = 0; nt < 4; nt++)
            #pragma unroll
            for (int i = 0; i < 4; i++) acc[mt][nt][i] = 0.0f;

    const int np = HAS2 ? 8 : 4;
    int frr = tid >> 2, fsg = (tid & 3) * 2;

    float4 rA[2], rB[2];

    auto ldg = [&](int p) {
        int op = HAS2 ? (p >> 2) : 0;
        int kc = (p & 3) * 32;
        const float* ap;
        if (op == 0) ap = In1 + (size_t)sRow[frr] * in1Stride;
        else         ap = (const float*)sP2[frr];
        const float* bw = (op == 0) ? W1 : W2;
        int bst = (op == 0) ? w1Stride : w2Stride;
        #pragma unroll
        for (int q = 0; q < 2; q++) {
            int seg = fsg + q;
            rA[q] = *(const float4*)(ap + kc + seg * 4);
            rB[q] = *(const float4*)(bw + (size_t)frr * bst + kc + seg * 4);
        }
    };
    auto sts = [&](int p) {
        uint32_t* st  = sBase + (p & 1) * (4 * STAGE_WORDS);
        uint32_t* tAh = st;
        uint32_t* tAl = st + STAGE_WORDS;
        uint32_t* tBh = st + 2 * STAGE_WORDS;
        uint32_t* tBl = st + 3 * STAGE_WORDS;
        #pragma unroll
        for (int q = 0; q < 2; q++) {
            int seg = fsg + q;
            int wa = frr * RSTR + seg * 2;
            uint32_t lo0, lo1;
            uint32_t hi0 = packsplit(rA[q].x, rA[q].y, lo0);
            uint32_t hi1 = packsplit(rA[q].z, rA[q].w, lo1);
            tAh[wa] = hi0; tAh[wa + 1] = hi1;
            tAl[wa] = lo0; tAl[wa + 1] = lo1;
            uint32_t wl0, wl1;
            uint32_t wh0 = packsplit(rB[q].x, rB[q].y, wl0);
            uint32_t wh1 = packsplit(rB[q].z, rB[q].w, wl1);
            tBh[wa] = wh0; tBh[wa + 1] = wh1;
            tBl[wa] = wl0; tBl[wa + 1] = wl1;
        }
    };

    ldg(0);
    sts(0);
    if (np > 1) ldg(1);
    __syncthreads();

    for (int p = 0; p < np; p++) {
        if (p + 1 < np) sts(p + 1);
        if (p + 2 < np) ldg(p + 2);
        uint32_t* st  = sBase + (p & 1) * (4 * STAGE_WORDS);
        uint32_t* sAhi = st;
        uint32_t* sAlo = st + STAGE_WORDS;
        uint32_t* sBhi = st + 2 * STAGE_WORDS;
        uint32_t* sBlo = st + 3 * STAGE_WORDS;
        #pragma unroll
        for (int ks = 0; ks < 2; ks++) {
            int wb = ks * 8 + tg;
            uint32_t aH[2][4], aL[2][4];
            #pragma unroll
            for (int mt = 0; mt < 2; mt++) {
                int rb = (warpM * 32 + mt * 16 + g) * RSTR;
                aH[mt][0] = sAhi[rb + wb];
                aH[mt][1] = sAhi[rb + 8 * RSTR + wb];
                aH[mt][2] = sAhi[rb + wb + 4];
                aH[mt][3] = sAhi[rb + 8 * RSTR + wb + 4];
                aL[mt][0] = sAlo[rb + wb];
                aL[mt][1] = sAlo[rb + 8 * RSTR + wb];
                aL[mt][2] = sAlo[rb + wb + 4];
                aL[mt][3] = sAlo[rb + 8 * RSTR + wb + 4];
            }
            #pragma unroll
            for (int nt = 0; nt < 4; nt++) {
                int nb = (warpN * 32 + nt * 8 + g) * RSTR;
                uint32_t bh0 = sBhi[nb + wb], bh1 = sBhi[nb + wb + 4];
                uint32_t bl0 = sBlo[nb + wb], bl1 = sBlo[nb + wb + 4];
                #pragma unroll
                for (int mt = 0; mt < 2; mt++) {
                    mma16(acc[mt][nt], aH[mt], bh0, bh1);
                    mma16(acc[mt][nt], aL[mt], bh0, bh1);
                    mma16(acc[mt][nt], aH[mt], bl0, bl1);
                }
            }
        }
        __syncthreads();
    }

    #pragma unroll
    for (int mt = 0; mt < 2; mt++) {
        #pragma unroll
        for (int half = 0; half < 2; half++) {
            int lr = warpM * 32 + mt * 16 + g + half * 8;
            int grow = row0 + lr;
            if (grow < nrows) {
                int orow = GOUT ? sRow[lr] : grow;
                float* ob = Out + (size_t)orow * 128;
                #pragma unroll
                for (int nt = 0; nt < 4; nt++) {
                    int col = warpN * 32 + nt * 8 + tg * 2;
                    float v0 = acc[mt][nt][half * 2 + 0];
                    float v1 = acc[mt][nt][half * 2 + 1];
                    if (HASBIAS) { v0 += sBias[col]; v1 += sBias[col + 1]; }
                    if (RELU) { v0 = fmaxf(v0, 0.0f); v1 = fmaxf(v1, 0.0f); }
                    float2 pp; pp.x = v0; pp.y = v1;
                    *(float2*)(ob + col) = pp;
                }
            }
        }
    }
}

// ---------------- host orchestration -------------------------------------------
extern "C" void kernel_launch(void* const* d_in, const int* in_sizes, int n_in,
                              void* d_out, int out_size) {
    int iXI, iXA, iPF, iPOP, iEIA, iEIF, iPROJ, iAGGW, iAGGB,
        iWL1, iBL1, iWR1, iWL2, iBL2, iWR2, iWL3, iBL3, iWR3;
    if (in_sizes[3] == PP) {  // setup_inputs dict order
        iXI = 0; iXA = 1; iPF = 2; iPOP = 3; iEIA = 4; iEIF = 5;
        iPROJ = 6; iAGGW = 7; iAGGB = 8; iWL1 = 9; iBL1 = 10; iWR1 = 11;
        iWL2 = 12; iBL2 = 13; iWR2 = 14; iWL3 = 15; iBL3 = 16; iWR3 = 17;
    } else {                  // reference() signature order
        iXI = 0; iXA = 1; iPF = 2; iPROJ = 3; iAGGW = 4; iAGGB = 5;
        iWL1 = 6; iBL1 = 7; iWR1 = 8; iWL2 = 9; iBL2 = 10; iWR2 = 11;
        iWL3 = 12; iBL3 = 13; iWR3 = 14; iPOP = 15; iEIA = 16; iEIF = 17;
    }

    const float* xi   = (const float*)d_in[iXI];
    const float* xa   = (const float*)d_in[iXA];
    const float* pf   = (const float*)d_in[iPF];
    const int*   pop  = (const int*)d_in[iPOP];
    const int*   eia  = (const int*)d_in[iEIA];
    const int*   eif  = (const int*)d_in[iEIF];
    const float* proj = (const float*)d_in[iPROJ];
    const float* aggW = (const float*)d_in[iAGGW];
    const float* aggB = (const float*)d_in[iAGGB];
    const float* wl1  = (const float*)d_in[iWL1];
    const float* bl1  = (const float*)d_in[iBL1];
    const float* wr1  = (const float*)d_in[iWR1];
    const float* wl2  = (const float*)d_in[iWL2];
    const float* bl2  = (const float*)d_in[iBL2];
    const float* wr2  = (const float*)d_in[iWR2];
    const float* wl3  = (const float*)d_in[iWL3];
    const float* bl3  = (const float*)d_in[iBL3];
    const float* wr3  = (const float*)d_in[iWR3];

    float* out = (float*)d_out;  // [x_ind_out (N*D)] then [x_att_out (A*N*D)]

    float *hbuf, *xatt_b, *agg, *esf, *projT, *MT;
    int *fillp, *ipop;
    cudaGetSymbolAddress((void**)&hbuf,   g_hbuf);
    cudaGetSymbolAddress((void**)&xatt_b, g_xatt_b);
    cudaGetSymbolAddress((void**)&agg,    g_agg);
    cudaGetSymbolAddress((void**)&esf,    g_esf);
    cudaGetSymbolAddress((void**)&projT,  g_projT);
    cudaGetSymbolAddress((void**)&MT,     g_MT);
    cudaGetSymbolAddress((void**)&fillp,  g_fill);
    cudaGetSymbolAddress((void**)&ipop,   g_ipop);
    float* agg3 = agg + 3 * ND;

    cudaFuncSetAttribute(inv_kernel, cudaFuncAttributeMaxDynamicSharedMemorySize, 131072);
    cudaFuncSetAttribute(gemm_tc<false, false, false, false, false, false>,
                         cudaFuncAttributeMaxDynamicSharedMemorySize, GEMM_SMEM);
    cudaFuncSetAttribute(gemm_tc<true, true, false, true, true, false>,
                         cudaFuncAttributeMaxDynamicSharedMemorySize, GEMM_SMEM);
    cudaFuncSetAttribute(gemm_tc<true, false, false, false, true, true>,
                         cudaFuncAttributeMaxDynamicSharedMemorySize, GEMM_SMEM);
    cudaFuncSetAttribute(gemm_tc<false, true, true, true, false, false>,
                         cudaFuncAttributeMaxDynamicSharedMemorySize, GEMM_SMEM);
    cudaFuncSetAttribute(gemm_tc<true, false, false, false, true, false>,
                         cudaFuncAttributeMaxDynamicSharedMemorySize, GEMM_SMEM);

    const int gP = (PP + 127) / 128;  // 391
    const int gN = (NN + 127) / 128;  // 782
    const int eB = (EE + 255) / 256;
    const int nB = (NN + 7) / 8;

    // --- prep: transpose, inverse, ipop ---
    transpose_wt<<<AA, 256>>>(projT, proj);
    inv_kernel<<<AA, 1024, 131072>>>(proj);
    cudaMemsetAsync(ipop, 0, (size_t)NN * sizeof(int), 0);
    ipop_k<<<(PP + 255) / 256, 256>>>(pop);

    // --- CSR build for all 7 graphs ---
    cudaMemsetAsync(fillp, 0, (size_t)7 * NN * sizeof(int), 0);
    hist_k<<<dim3(eB, 7), 256>>>(eia, eif);
    scan_p1<<<dim3(NBLK, 7), 1024>>>();
    scan_p2<<<1, 256>>>();
    scan_p3<<<dim3(NBLK, 7), 1024>>>();
    fill_k<<<dim3(eB, 7), 256>>>(eia, eif);

    // 3) esf[a] = PF[:,a,:] @ proj[a]   (tensor-core GEMM; B = projT [o][i])
    gemm_tc<false, false, false, false, false, false><<<dim3(gP, AA), 512, GEMM_SMEM>>>(
        pf, AA * DD, (long)DD, projT, 128, 16384,
        nullptr, 0, 0, nullptr, 0, nullptr,
        nullptr, 0, 0,
        nullptr, 0, nullptr,
        esf, (long)PD, PP);

    // 4) hbuf[a][i] = relu(xa[a][pop[i]] @ aggW1^T + esf[a][i] @ aggW2^T + aggB)
    gemm_tc<true, true, false, true, true, false><<<dim3(gP, AA), 512, GEMM_SMEM>>>(
        xa, DD, (long)ND, aggW, 256, 0,
        esf, DD, (long)PD, nullptr, 0, nullptr,
        aggW + 128, 256, 0,
        aggB, 0, pop,
        hbuf, (long)PD, PP);

    // 5+10) agg = seg-mean of xi: graphs 0-2 (dst-seg) and 6 (family)
    gather_mean<<<dim3(nB, 4), 256>>>(xi, 0, 0, 1, agg, (long)ND);

    // 6) x_att_b = agg @ W_l1^T + b_l1 + x_att_a @ W_r1^T  (x_att_a via hbuf/xa select)
    gemm_tc<true, false, false, false, true, true><<<dim3(gN, AA), 512, GEMM_SMEM>>>(
        agg, DD, (long)ND, wl1, 128, 16384,
        xa, DD, (long)ND, hbuf, (long)PD, ipop,
        wr1, 128, 16384,
        bl1, DD, nullptr,
        xatt_b, (long)ND, NN);

    // 7) population rows: x_att_b[pop] = relu(x_att_b[pop] @ (inv(proj)+I))
    gemm_tc<false, true, true, true, false, false><<<dim3(gP, AA), 512, GEMM_SMEM>>>(
        xatt_b, DD, (long)ND, MT, 128, 16384,
        nullptr, 0, 0, nullptr, 0, nullptr,
        nullptr, 0, 0,
        nullptr, 0, pop,
        xatt_b, (long)ND, PP);

    // 8) agg = seg-mean of x_att_b over src (graphs 3-5)
    gather_mean<<<dim3(nB, AA), 256>>>(xatt_b, (long)ND, 3, 0, agg, (long)ND);

    // 9) x_att_out = agg @ W_l2^T + b_l2 + x_att_b @ W_r2^T  -> d_out[N*D:]
    gemm_tc<true, false, false, false, true, false><<<dim3(gN, AA), 512, GEMM_SMEM>>>(
        agg, DD, (long)ND, wl2, 128, 16384,
        xatt_b, DD, (long)ND, nullptr, 0, nullptr,
        wr2, 128, 16384,
        bl2, DD, nullptr,
        out + ND, (long)ND, NN);

    // 11) x_ind_out = agg3 @ W_l3^T + b_l3 + xi @ W_r3^T -> d_out[0:]
    gemm_tc<true, false, false, false, true, false><<<dim3(gN, 1), 512, GEMM_SMEM>>>(
        agg3, DD, 0, wl3, 128, 0,
        xi, DD, 0, nullptr, 0, nullptr,
        wr3, 128, 0,
        bl3, 0, nullptr,
        out, 0, NN);
}

// round 13
// speedup vs baseline: 1.5035x; 1.0001x over previous
#include <cuda_runtime.h>
#include <cuda_bf16.h>
#include <cstdint>
#include <cstddef>

#define NN 100000
#define DD 128
#define AA 3
#define PP 50000
#define EE 500000
#define EFN 500000

#define ND  ((size_t)NN * DD)
#define AND ((size_t)AA * NN * DD)
#define PD  ((size_t)PP * DD)
#define NBLK 98   // (NN + 1023) / 1024

// ---------------- scratch (static device globals; no allocation) ----------------
__device__ float  g_hbuf  [AA * PP * DD];    // compact h rows (population)
__device__ float  g_xatt_b[AA * NN * DD];
__device__ float  g_agg   [4 * NN * DD];     // slots 0-2: attr agg; slot 3: family agg
__device__ float  g_esf   [AA * PP * DD];
__device__ float  g_projT [AA * 128 * 128];  // proj^T: [o][i]
__device__ float  g_MT    [AA * 128 * 128];  // (inv(proj)+I)^T: [o][i]
__device__ int    g_ipop  [NN];              // node -> pop position+1 (0 = absent)
// CSR structures for the 7 edge graphs (0-2: attr dst-seg, 3-5: attr src-seg, 6: family)
__device__ int    g_rowptr[7 * (NN + 1)];
__device__ int    g_fill  [7 * NN];
__device__ int    g_eord  [7 * EE];
__device__ int    g_bsum  [7 * NBLK];

// m16n8k16 bf16 mma (sm_80+ portable)
__device__ __forceinline__ void mma16(float* c, const uint32_t* a, uint32_t b0, uint32_t b1) {
    asm volatile("mma.sync.aligned.m16n8k16.row.col.f32.bf16.bf16.f32 "
                 "{%0,%1,%2,%3}, {%4,%5,%6,%7}, {%8,%9}, {%0,%1,%2,%3};"
                 : "+f"(c[0]), "+f"(c[1]), "+f"(c[2]), "+f"(c[3])
                 : "r"(a[0]), "r"(a[1]), "r"(a[2]), "r"(a[3]), "r"(b0), "r"(b1));
}
// split (x,y) into packed bf16x2 hi + lo
__device__ __forceinline__ uint32_t packsplit(float x, float y, uint32_t& lopack) {
    float hx = __bfloat162float(__float2bfloat16(x));
    float hy = __bfloat162float(__float2bfloat16(y));
    uint32_t hi;
    asm("cvt.rn.bf16x2.f32 %0, %1, %2;" : "=r"(hi) : "f"(hy), "f"(hx));
    asm("cvt.rn.bf16x2.f32 %0, %1, %2;" : "=r"(lopack) : "f"(y - hy), "f"(x - hx));
    return hi;
}

// ---------------- weight transpose: dst[b][o][i] = src[b][i][o] -----------------
__global__ void transpose_wt(float* __restrict__ dst, const float* __restrict__ src) {
    int b = blockIdx.x;
    const float* s = src + (size_t)b * 16384;
    float* d = dst + (size_t)b * 16384;
    for (int idx = threadIdx.x; idx < 16384; idx += blockDim.x) {
        int o = idx >> 7, i = idx & 127;
        d[idx] = s[(size_t)i * 128 + o];
    }
}

// ---------------- ipop: node -> population position + 1 -------------------------
__global__ void ipop_k(const int* __restrict__ pop) {
    int i = blockIdx.x * blockDim.x + threadIdx.x;
    if (i < PP) g_ipop[pop[i]] = i + 1;
}

// ---------------- fp64 in-place Gauss-Jordan inverse, all in SMEM ---------------
__global__ __launch_bounds__(1024)
void inv_kernel(const float* __restrict__ proj) {
    extern __shared__ double S[];            // 128*128
    __shared__ double pv[128];
    __shared__ int    pi[128];
    __shared__ int    perm[128];

    int a = blockIdx.x;
    int tid = threadIdx.x;
    int c = tid & 127, r0 = (tid >> 7) << 4;

    for (int idx = tid; idx < 16384; idx += 1024)
        S[idx] = (double)proj[(size_t)a * 16384 + idx];
    __syncthreads();

    for (int k = 0; k < 128; k++) {
        if (tid < 128) {
            pv[tid] = (tid >= k) ? fabs(S[tid * 128 + k]) : -1.0;
            pi[tid] = tid;
        }
        __syncthreads();
        for (int s = 64; s > 0; s >>= 1) {
            if (tid < s && pv[tid + s] > pv[tid]) { pv[tid] = pv[tid + s]; pi[tid] = pi[tid + s]; }
            __syncthreads();
        }
        int piv = pi[0];
        if (tid == 0) perm[k] = piv;
        if (tid < 128) {
            double vk = S[k * 128 + tid];
            if (piv != k) {
                double vp = S[piv * 128 + tid];
                S[piv * 128 + tid] = vk;
                vk = vp;
            }
            pv[tid] = vk;
        }
        __syncthreads();
        double d = pv[k];
        if (tid < 128) {
            double nv = ((tid == k) ? 1.0 : pv[tid]) / d;
            S[k * 128 + tid] = nv;
            pv[tid] = nv;
        }
        __syncthreads();
        double rk = pv[c];
        double f[16];
        #pragma unroll
        for (int m = 0; m < 16; m++) {
            int r = r0 + m;
            f[m] = (r == k) ? 0.0 : S[r * 128 + k];
        }
        __syncthreads();
        #pragma unroll
        for (int m = 0; m < 16; m++) {
            int r = r0 + m;
            if (r != k) {
                double v = S[r * 128 + c];
                if (c == k) v = 0.0;
                S[r * 128 + c] = v - f[m] * rk;
            }
        }
        __syncthreads();
    }
    for (int k = 127; k >= 0; k--) {
        int p = perm[k];
        if (p != k && tid < 128) {
            double t = S[tid * 128 + k];
            S[tid * 128 + k] = S[tid * 128 + p];
            S[tid * 128 + p] = t;
        }
        __syncthreads();
    }
    for (int idx = tid; idx < 16384; idx += 1024) {
        int o = idx >> 7, i = idx & 127;
        g_MT[(size_t)a * 16384 + idx] = (float)(S[i * 128 + o] + (i == o ? 1.0 : 0.0));
    }
}

// ---------------- CSR build ------------------------------------------------------
__device__ __forceinline__ void graph_ptrs(int g, const int* eia, const int* eif,
                                           const int** gi, const int** si) {
    if (g < 3)      { *gi = eia + (size_t)g * 2 * EE;            *si = eia + (size_t)g * 2 * EE + EE; }
    else if (g < 6) { *gi = eia + (size_t)(g - 3) * 2 * EE + EE; *si = eia + (size_t)(g - 3) * 2 * EE; }
    else            { *gi = eif + EFN;                           *si = eif; }
}

__global__ void hist_k(const int* __restrict__ eia, const int* __restrict__ eif) {
    int g = blockIdx.y;
    const int *gi, *si;
    graph_ptrs(g, eia, eif, &gi, &si);
    int e = blockIdx.x * blockDim.x + threadIdx.x;
    if (e < EE) atomicAdd(g_fill + (size_t)g * NN + si[e], 1);
}

// pass 1: per-block sums
__global__ __launch_bounds__(1024)
void scan_p1() {
    int g = blockIdx.y, b = blockIdx.x, tid = threadIdx.x;
    int i = b * 1024 + tid;
    int v = (i < NN) ? g_fill[(size_t)g * NN + i] : 0;
    #pragma unroll
    for (int o = 16; o; o >>= 1) v += __shfl_down_sync(~0u, v, o);
    __shared__ int w[32];
    if ((tid & 31) == 0) w[tid >> 5] = v;
    __syncthreads();
    if (tid < 32) {
        int x = w[tid];
        #pragma unroll
        for (int o = 16; o; o >>= 1) x += __shfl_down_sync(~0u, x, o);
        if (tid == 0) g_bsum[g * NBLK + b] = x;
    }
}
// pass 2: scan block sums (7 graphs, one lane each)
__global__ void scan_p2() {
    int wid = threadIdx.x >> 5, lane = threadIdx.x & 31;
    if (wid < 7 && lane == 0) {
        int run = 0;
        for (int j = 0; j < NBLK; j++) {
            int t = g_bsum[wid * NBLK + j];
            g_bsum[wid * NBLK + j] = run;
            run += t;
        }
        g_rowptr[(size_t)wid * (NN + 1) + NN] = run;
    }
}
// pass 3: block-local exclusive scan + base; writes rowptr and fill cursors
__global__ __launch_bounds__(1024)
void scan_p3() {
    int g = blockIdx.y, b = blockIdx.x, tid = threadIdx.x;
    int i = b * 1024 + tid;
    int v = (i < NN) ? g_fill[(size_t)g * NN + i] : 0;
    __shared__ int s[1024];
    s[tid] = v;
    __syncthreads();
    for (int off = 1; off < 1024; off <<= 1) {
        int t = (tid >= off) ? s[tid - off] : 0;
        __syncthreads();
        s[tid] += t;
        __syncthreads();
    }
    if (i < NN) {
        int val = g_bsum[g * NBLK + b] + s[tid] - v;
        g_rowptr[(size_t)g * (NN + 1) + i] = val;
        g_fill[(size_t)g * NN + i] = val;
    }
}

__global__ void fill_k(const int* __restrict__ eia, const int* __restrict__ eif) {
    int g = blockIdx.y;
    const int *gi, *si;
    graph_ptrs(g, eia, eif, &gi, &si);
    int e = blockIdx.x * blockDim.x + threadIdx.x;
    if (e < EE) {
        int pos = atomicAdd(g_fill + (size_t)g * NN + si[e], 1);
        g_eord[(size_t)g * EE + pos] = gi[e];
    }
}

// ---------------- gather-mean ----------------------------------------------------
__global__ __launch_bounds__(256)
void gather_mean(const float* __restrict__ data, long dataBStr,
                 int gbase, int fam4, float* __restrict__ outp, long outBStr) {
    int a = blockIdx.y;
    int g = (fam4 && a == 3) ? 6 : (gbase + a);
    const float* d = data + (size_t)a * dataBStr;
    float* o = outp + (size_t)a * outBStr;
    const int* rp = g_rowptr + (size_t)g * (NN + 1);
    const int* eo = g_eord + (size_t)g * EE;

    int node = blockIdx.x * 8 + (threadIdx.x >> 5);
    int lane = threadIdx.x & 31;
    if (node >= NN) return;
    int s = rp[node], e = rp[node + 1];
    float4 acc = make_float4(0.f, 0.f, 0.f, 0.f);
    int j = s;
    for (; j + 1 < e; j += 2) {
        int g0 = eo[j], g1 = eo[j + 1];
        float4 v0 = ((const float4*)(d + (size_t)g0 * DD))[lane];
        float4 v1 = ((const float4*)(d + (size_t)g1 * DD))[lane];
        acc.x += v0.x + v1.x; acc.y += v0.y + v1.y;
        acc.z += v0.z + v1.z; acc.w += v0.w + v1.w;
    }
    if (j < e) {
        float4 v = ((const float4*)(d + (size_t)eo[j] * DD))[lane];
        acc.x += v.x; acc.y += v.y; acc.z += v.z; acc.w += v.w;
    }
    float inv = 1.0f / fmaxf((float)(e - s), 1.0f);
    acc.x *= inv; acc.y *= inv; acc.z *= inv; acc.w *= inv;
    ((float4*)(o + (size_t)node * DD))[lane] = acc;
}

// ---------------- bf16 m16n8k16 fused GEMM, double-buffered ----------------------
// Out[row] = act( In1[row] @ W1^T + In2row @ W2^T + bias )
// GIN: In1 rows (and GOUT: Out rows) indirected via ridx. SEL2: In2 row r taken
// from In2b[sel2[r]-1] when sel2[r]>0 else In2[r]. In2 row pointers live in a
// shared table (sP2) so the mainloop carries no extra registers.
#define RSTR 20
static constexpr int STAGE_WORDS = 128 * RSTR;
static constexpr int GEMM_SMEM = 2048 + 2 * 4 * STAGE_WORDS * 4;   // 83968

template<bool HAS2, bool GIN, bool GOUT, bool RELU, bool HASBIAS, bool SEL2>
__global__ __launch_bounds__(512)
void gemm_tc(const float* __restrict__ In1, int in1Stride, long in1BStr,
             const float* __restrict__ W1, int w1Stride, long w1BStr,
             const float* __restrict__ In2, int in2Stride, long in2BStr,
             const float* __restrict__ In2b, long in2bBStr, const int* __restrict__ sel2,
             const float* __restrict__ W2, int w2Stride, long w2BStr,
             const float* __restrict__ bias, long biasBStr,
             const int*   __restrict__ ridx,
             float* __restrict__ Out, long outBStr, int nrows) {
    extern __shared__ __align__(16) char smem[];
    int*      sRow  = (int*)smem;                            // 512 B
    float*    sBias = (float*)(smem + 512);                  // 512 B
    unsigned long long* sP2 = (unsigned long long*)(smem + 1024);  // 1024 B
    uint32_t* sBase = (uint32_t*)(smem + 2048);

    {
        long a = blockIdx.y;
        In1 += a * in1BStr; W1 += a * w1BStr;
        if (HAS2) { In2 += a * in2BStr; W2 += a * w2BStr; }
        if (SEL2) In2b += a * in2bBStr;
        if (HASBIAS) bias += a * biasBStr;
        Out += a * outBStr;
    }

    int tid = threadIdx.x, wid = tid >> 5, lane = tid & 31;
    int g = lane >> 2, tg = lane & 3;
    int warpM = wid >> 2, warpN = wid & 3;
    int row0 = blockIdx.x * 128;

    if (tid < 128) {
        int gr = row0 + tid;
        int e = 0;
        if (gr < nrows) e = GIN ? ridx[gr] : gr;
        sRow[tid] = e;
        if (HASBIAS) sBias[tid] = bias[tid];
        if (HAS2) {
            int g2 = (gr < nrows) ? gr : (nrows - 1);
            const float* p;
            if (SEL2) {
                int s2 = sel2[g2];
                p = (s2 > 0) ? In2b + (size_t)(s2 - 1) * DD
                             : In2 + (size_t)g2 * in2Stride;
            } else {
                p = In2 + (size_t)g2 * in2Stride;
            }
            sP2[tid] = (unsigned long long)p;
        }
    }
    __syncthreads();

    float acc[2][4][4];
    #pragma unroll
    for (int mt = 0; mt < 2; mt++)
        #pragma unroll
        for (int nt = 0; nt < 4; nt++)
            #pragma unroll
            for (int i = 0; i < 4; i++) acc[mt][nt][i] = 0.0f;

    const int np = HAS2 ? 8 : 4;
    int frr = tid >> 2, fsg = (tid & 3) * 2;

    float4 rA[2], rB[2];

    auto ldg = [&](int p) {
        int op = HAS2 ? (p >> 2) : 0;
        int kc = (p & 3) * 32;
        const float* ap;
        if (op == 0) ap = In1 + (size_t)sRow[frr] * in1Stride;
        else         ap = (const float*)sP2[frr];
        const float* bw = (op == 0) ? W1 : W2;
        int bst = (op == 0) ? w1Stride : w2Stride;
        #pragma unroll
        for (int q = 0; q < 2; q++) {
            int seg = fsg + q;
            rA[q] = *(const float4*)(ap + kc + seg * 4);
            rB[q] = *(const float4*)(bw + (size_t)frr * bst + kc + seg * 4);
        }
    };
    auto sts = [&](int p) {
        uint32_t* st  = sBase + (p & 1) * (4 * STAGE_WORDS);
        uint32_t* tAh = st;
        uint32_t* tAl = st + STAGE_WORDS;
        uint32_t* tBh = st + 2 * STAGE_WORDS;
        uint32_t* tBl = st + 3 * STAGE_WORDS;
        #pragma unroll
        for (int q = 0; q < 2; q++) {
            int seg = fsg + q;
            int wa = frr * RSTR + seg * 2;
            uint32_t lo0, lo1;
            uint32_t hi0 = packsplit(rA[q].x, rA[q].y, lo0);
            uint32_t hi1 = packsplit(rA[q].z, rA[q].w, lo1);
            tAh[wa] = hi0; tAh[wa + 1] = hi1;
            tAl[wa] = lo0; tAl[wa + 1] = lo1;
            uint32_t wl0, wl1;
            uint32_t wh0 = packsplit(rB[q].x, rB[q].y, wl0);
            uint32_t wh1 = packsplit(rB[q].z, rB[q].w, wl1);
            tBh[wa] = wh0; tBh[wa + 1] = wh1;
            tBl[wa] = wl0; tBl[wa + 1] = wl1;
        }
    };

    ldg(0);
    sts(0);
    if (np > 1) ldg(1);
    __syncthreads();

    for (int p = 0; p < np; p++) {
        if (p + 1 < np) sts(p + 1);
        if (p + 2 < np) ldg(p + 2);
        uint32_t* st  = sBase + (p & 1) * (4 * STAGE_WORDS);
        uint32_t* sAhi = st;
        uint32_t* sAlo = st + STAGE_WORDS;
        uint32_t* sBhi = st + 2 * STAGE_WORDS;
        uint32_t* sBlo = st + 3 * STAGE_WORDS;
        #pragma unroll
        for (int ks = 0; ks < 2; ks++) {
            int wb = ks * 8 + tg;
            uint32_t aH[2][4], aL[2][4];
            #pragma unroll
            for (int mt = 0; mt < 2; mt++) {
                int rb = (warpM * 32 + mt * 16 + g) * RSTR;
                aH[mt][0] = sAhi[rb + wb];
                aH[mt][1] = sAhi[rb + 8 * RSTR + wb];
                aH[mt][2] = sAhi[rb + wb + 4];
                aH[mt][3] = sAhi[rb + 8 * RSTR + wb + 4];
                aL[mt][0] = sAlo[rb + wb];
                aL[mt][1] = sAlo[rb + 8 * RSTR + wb];
                aL[mt][2] = sAlo[rb + wb + 4];
                aL[mt][3] = sAlo[rb + 8 * RSTR + wb + 4];
            }
            #pragma unroll
            for (int nt = 0; nt < 4; nt++) {
                int nb = (warpN * 32 + nt * 8 + g) * RSTR;
                uint32_t bh0 = sBhi[nb + wb], bh1 = sBhi[nb + wb + 4];
                uint32_t bl0 = sBlo[nb + wb], bl1 = sBlo[nb + wb + 4];
                #pragma unroll
                for (int mt = 0; mt < 2; mt++) {
                    mma16(acc[mt][nt], aH[mt], bh0, bh1);
                    mma16(acc[mt][nt], aL[mt], bh0, bh1);
                    mma16(acc[mt][nt], aH[mt], bl0, bl1);
                }
            }
        }
        __syncthreads();
    }

    #pragma unroll
    for (int mt = 0; mt < 2; mt++) {
        #pragma unroll
        for (int half = 0; half < 2; half++) {
            int lr = warpM * 32 + mt * 16 + g + half * 8;
            int grow = row0 + lr;
            if (grow < nrows) {
                int orow = GOUT ? sRow[lr] : grow;
                float* ob = Out + (size_t)orow * 128;
                #pragma unroll
                for (int nt = 0; nt < 4; nt++) {
                    int col = warpN * 32 + nt * 8 + tg * 2;
                    float v0 = acc[mt][nt][half * 2 + 0];
                    float v1 = acc[mt][nt][half * 2 + 1];
                    if (HASBIAS) { v0 += sBias[col]; v1 += sBias[col + 1]; }
                    if (RELU) { v0 = fmaxf(v0, 0.0f); v1 = fmaxf(v1, 0.0f); }
                    float2 pp; pp.x = v0; pp.y = v1;
                    *(float2*)(ob + col) = pp;
                }
            }
        }
    }
}

// ---------------- host orchestration -------------------------------------------
extern "C" void kernel_launch(void* const* d_in, const int* in_sizes, int n_in,
                              void* d_out, int out_size) {
    int iXI, iXA, iPF, iPOP, iEIA, iEIF, iPROJ, iAGGW, iAGGB,
        iWL1, iBL1, iWR1, iWL2, iBL2, iWR2, iWL3, iBL3, iWR3;
    if (in_sizes[3] == PP) {  // setup_inputs dict order
        iXI = 0; iXA = 1; iPF = 2; iPOP = 3; iEIA = 4; iEIF = 5;
        iPROJ = 6; iAGGW = 7; iAGGB = 8; iWL1 = 9; iBL1 = 10; iWR1 = 11;
        iWL2 = 12; iBL2 = 13; iWR2 = 14; iWL3 = 15; iBL3 = 16; iWR3 = 17;
    } else {                  // reference() signature order
        iXI = 0; iXA = 1; iPF = 2; iPROJ = 3; iAGGW = 4; iAGGB = 5;
        iWL1 = 6; iBL1 = 7; iWR1 = 8; iWL2 = 9; iBL2 = 10; iWR2 = 11;
        iWL3 = 12; iBL3 = 13; iWR3 = 14; iPOP = 15; iEIA = 16; iEIF = 17;
    }

    const float* xi   = (const float*)d_in[iXI];
    const float* xa   = (const float*)d_in[iXA];
    const float* pf   = (const float*)d_in[iPF];
    const int*   pop  = (const int*)d_in[iPOP];
    const int*   eia  = (const int*)d_in[iEIA];
    const int*   eif  = (const int*)d_in[iEIF];
    const float* proj = (const float*)d_in[iPROJ];
    const float* aggW = (const float*)d_in[iAGGW];
    const float* aggB = (const float*)d_in[iAGGB];
    const float* wl1  = (const float*)d_in[iWL1];
    const float* bl1  = (const float*)d_in[iBL1];
    const float* wr1  = (const float*)d_in[iWR1];
    const float* wl2  = (const float*)d_in[iWL2];
    const float* bl2  = (const float*)d_in[iBL2];
    const float* wr2  = (const float*)d_in[iWR2];
    const float* wl3  = (const float*)d_in[iWL3];
    const float* bl3  = (const float*)d_in[iBL3];
    const float* wr3  = (const float*)d_in[iWR3];

    float* out = (float*)d_out;  // [x_ind_out (N*D)] then [x_att_out (A*N*D)]

    float *hbuf, *xatt_b, *agg, *esf, *projT, *MT;
    int *fillp, *ipop;
    cudaGetSymbolAddress((void**)&hbuf,   g_hbuf);
    cudaGetSymbolAddress((void**)&xatt_b, g_xatt_b);
    cudaGetSymbolAddress((void**)&agg,    g_agg);
    cudaGetSymbolAddress((void**)&esf,    g_esf);
    cudaGetSymbolAddress((void**)&projT,  g_projT);
    cudaGetSymbolAddress((void**)&MT,     g_MT);
    cudaGetSymbolAddress((void**)&fillp,  g_fill);
    cudaGetSymbolAddress((void**)&ipop,   g_ipop);
    float* agg3 = agg + 3 * ND;

    cudaFuncSetAttribute(inv_kernel, cudaFuncAttributeMaxDynamicSharedMemorySize, 131072);
    cudaFuncSetAttribute(gemm_tc<false, false, false, false, false, false>,
                         cudaFuncAttributeMaxDynamicSharedMemorySize, GEMM_SMEM);
    cudaFuncSetAttribute(gemm_tc<true, true, false, true, true, false>,
                         cudaFuncAttributeMaxDynamicSharedMemorySize, GEMM_SMEM);
    cudaFuncSetAttribute(gemm_tc<true, false, false, false, true, true>,
                         cudaFuncAttributeMaxDynamicSharedMemorySize, GEMM_SMEM);
    cudaFuncSetAttribute(gemm_tc<false, true, true, true, false, false>,
                         cudaFuncAttributeMaxDynamicSharedMemorySize, GEMM_SMEM);
    cudaFuncSetAttribute(gemm_tc<true, false, false, false, true, false>,
                         cudaFuncAttributeMaxDynamicSharedMemorySize, GEMM_SMEM);

    const int gP = (PP + 127) / 128;  // 391
    const int gN = (NN + 127) / 128;  // 782
    const int eB = (EE + 255) / 256;
    const int nB = (NN + 7) / 8;

    // --- prep: transpose, inverse, ipop ---
    transpose_wt<<<AA, 256>>>(projT, proj);
    inv_kernel<<<AA, 1024, 131072>>>(proj);
    cudaMemsetAsync(ipop, 0, (size_t)NN * sizeof(int), 0);
    ipop_k<<<(PP + 255) / 256, 256>>>(pop);

    // --- CSR build for all 7 graphs ---
    cudaMemsetAsync(fillp, 0, (size_t)7 * NN * sizeof(int), 0);
    hist_k<<<dim3(eB, 7), 256>>>(eia, eif);
    scan_p1<<<dim3(NBLK, 7), 1024>>>();
    scan_p2<<<1, 256>>>();
    scan_p3<<<dim3(NBLK, 7), 1024>>>();
    fill_k<<<dim3(eB, 7), 256>>>(eia, eif);

    // 3) esf[a] = PF[:,a,:] @ proj[a]   (tensor-core GEMM; B = projT [o][i])
    gemm_tc<false, false, false, false, false, false><<<dim3(gP, AA), 512, GEMM_SMEM>>>(
        pf, AA * DD, (long)DD, projT, 128, 16384,
        nullptr, 0, 0, nullptr, 0, nullptr,
        nullptr, 0, 0,
        nullptr, 0, nullptr,
        esf, (long)PD, PP);

    // 4) hbuf[a][i] = relu(xa[a][pop[i]] @ aggW1^T + esf[a][i] @ aggW2^T + aggB)
    gemm_tc<true, true, false, true, true, false><<<dim3(gP, AA), 512, GEMM_SMEM>>>(
        xa, DD, (long)ND, aggW, 256, 0,
        esf, DD, (long)PD, nullptr, 0, nullptr,
        aggW + 128, 256, 0,
        aggB, 0, pop,
        hbuf, (long)PD, PP);

    // 5+10) agg = seg-mean of xi: graphs 0-2 (dst-seg) and 6 (family)
    gather_mean<<<dim3(nB, 4), 256>>>(xi, 0, 0, 1, agg, (long)ND);

    // 6) x_att_b = agg @ W_l1^T + b_l1 + x_att_a @ W_r1^T  (x_att_a via hbuf/xa select)
    gemm_tc<true, false, false, false, true, true><<<dim3(gN, AA), 512, GEMM_SMEM>>>(
        agg, DD, (long)ND, wl1, 128, 16384,
        xa, DD, (long)ND, hbuf, (long)PD, ipop,
        wr1, 128, 16384,
        bl1, DD, nullptr,
        xatt_b, (long)ND, NN);

    // 7) population rows: x_att_b[pop] = relu(x_att_b[pop] @ (inv(proj)+I))
    gemm_tc<false, true, true, true, false, false><<<dim3(gP, AA), 512, GEMM_SMEM>>>(
        xatt_b, DD, (long)ND, MT, 128, 16384,
        nullptr, 0, 0, nullptr, 0, nullptr,
        nullptr, 0, 0,
        nullptr, 0, pop,
        xatt_b, (long)ND, PP);

    // 8) agg = seg-mean of x_att_b over src (graphs 3-5)
    gather_mean<<<dim3(nB, AA), 256>>>(xatt_b, (long)ND, 3, 0, agg, (long)ND);

    // 9) x_att_out = agg @ W_l2^T + b_l2 + x_att_b @ W_r2^T  -> d_out[N*D:]
    gemm_tc<true, false, false, false, true, false><<<dim3(gN, AA), 512, GEMM_SMEM>>>(
        agg, DD, (long)ND, wl2, 128, 16384,
        xatt_b, DD, (long)ND, nullptr, 0, nullptr,
        wr2, 128, 16384,
        bl2, DD, nullptr,
        out + ND, (long)ND, NN);

    // 11) x_ind_out = agg3 @ W_l3^T + b_l3 + xi @ W_r3^T -> d_out[0:]
    gemm_tc<true, false, false, false, true, false><<<dim3(gN, 1), 512, GEMM_SMEM>>>(
        agg3, DD, 0, wl3, 128, 0,
        xi, DD, 0, nullptr, 0, nullptr,
        wr3, 128, 0,
        bl3, 0, nullptr,
        out, 0, NN);
}

// round 14
// speedup vs baseline: 1.5044x; 1.0006x over previous
#include <cuda_runtime.h>
#include <cuda_bf16.h>
#include <cstdint>
#include <cstddef>

#define NN 100000
#define DD 128
#define AA 3
#define PP 50000
#define EE 500000
#define EFN 500000

#define ND  ((size_t)NN * DD)
#define AND ((size_t)AA * NN * DD)
#define PD  ((size_t)PP * DD)
#define NBLK 98   // (NN + 1023) / 1024

// ---------------- scratch (static device globals; no allocation) ----------------
__device__ float  g_hbuf  [AA * PP * DD];    // compact h rows (population)
__device__ float  g_xatt_b[AA * NN * DD];
__device__ float  g_agg   [4 * NN * DD];     // slots 0-2: attr agg; slot 3: family agg
__device__ float  g_esf   [AA * PP * DD];
__device__ float  g_projT [AA * 128 * 128];  // proj^T: [o][i]
__device__ float  g_MT    [AA * 128 * 128];  // (inv(proj)+I)^T: [o][i]
__device__ int    g_ipop  [NN];              // node -> pop position+1 (0 = absent)
// CSR structures for the 7 edge graphs (0-2: attr dst-seg, 3-5: attr src-seg, 6: family)
__device__ int    g_rowptr[7 * (NN + 1)];
__device__ int    g_fill  [7 * NN];
__device__ int    g_eord  [7 * EE];
__device__ int    g_bsum  [7 * NBLK];

// m16n8k16 bf16 mma (sm_80+ portable)
__device__ __forceinline__ void mma16(float* c, const uint32_t* a, uint32_t b0, uint32_t b1) {
    asm volatile("mma.sync.aligned.m16n8k16.row.col.f32.bf16.bf16.f32 "
                 "{%0,%1,%2,%3}, {%4,%5,%6,%7}, {%8,%9}, {%0,%1,%2,%3};"
                 : "+f"(c[0]), "+f"(c[1]), "+f"(c[2]), "+f"(c[3])
                 : "r"(a[0]), "r"(a[1]), "r"(a[2]), "r"(a[3]), "r"(b0), "r"(b1));
}
// split (x,y) into packed bf16x2 hi + lo
__device__ __forceinline__ uint32_t packsplit(float x, float y, uint32_t& lopack) {
    float hx = __bfloat162float(__float2bfloat16(x));
    float hy = __bfloat162float(__float2bfloat16(y));
    uint32_t hi;
    asm("cvt.rn.bf16x2.f32 %0, %1, %2;" : "=r"(hi) : "f"(hy), "f"(hx));
    asm("cvt.rn.bf16x2.f32 %0, %1, %2;" : "=r"(lopack) : "f"(y - hy), "f"(x - hx));
    return hi;
}

// ---------------- weight transpose: dst[b][o][i] = src[b][i][o] -----------------
__global__ void transpose_wt(float* __restrict__ dst, const float* __restrict__ src) {
    int b = blockIdx.x;
    const float* s = src + (size_t)b * 16384;
    float* d = dst + (size_t)b * 16384;
    for (int idx = threadIdx.x; idx < 16384; idx += blockDim.x) {
        int o = idx >> 7, i = idx & 127;
        d[idx] = s[(size_t)i * 128 + o];
    }
}

// ---------------- ipop: node -> population position + 1 -------------------------
__global__ void ipop_k(const int* __restrict__ pop) {
    int i = blockIdx.x * blockDim.x + threadIdx.x;
    if (i < PP) g_ipop[pop[i]] = i + 1;
}

// ---------------- fp64 in-place Gauss-Jordan inverse, all in SMEM ---------------
__global__ __launch_bounds__(1024)
void inv_kernel(const float* __restrict__ proj) {
    extern __shared__ double S[];            // 128*128
    __shared__ double pv[128];
    __shared__ int    pi[128];
    __shared__ int    perm[128];

    int a = blockIdx.x;
    int tid = threadIdx.x;
    int c = tid & 127, r0 = (tid >> 7) << 4;

    for (int idx = tid; idx < 16384; idx += 1024)
        S[idx] = (double)proj[(size_t)a * 16384 + idx];
    __syncthreads();

    for (int k = 0; k < 128; k++) {
        if (tid < 128) {
            pv[tid] = (tid >= k) ? fabs(S[tid * 128 + k]) : -1.0;
            pi[tid] = tid;
        }
        __syncthreads();
        for (int s = 64; s > 0; s >>= 1) {
            if (tid < s && pv[tid + s] > pv[tid]) { pv[tid] = pv[tid + s]; pi[tid] = pi[tid + s]; }
            __syncthreads();
        }
        int piv = pi[0];
        if (tid == 0) perm[k] = piv;
        if (tid < 128) {
            double vk = S[k * 128 + tid];
            if (piv != k) {
                double vp = S[piv * 128 + tid];
                S[piv * 128 + tid] = vk;
                vk = vp;
            }
            pv[tid] = vk;
        }
        __syncthreads();
        double d = pv[k];
        if (tid < 128) {
            double nv = ((tid == k) ? 1.0 : pv[tid]) / d;
            S[k * 128 + tid] = nv;
            pv[tid] = nv;
        }
        __syncthreads();
        double rk = pv[c];
        double f[16];
        #pragma unroll
        for (int m = 0; m < 16; m++) {
            int r = r0 + m;
            f[m] = (r == k) ? 0.0 : S[r * 128 + k];
        }
        __syncthreads();
        #pragma unroll
        for (int m = 0; m < 16; m++) {
            int r = r0 + m;
            if (r != k) {
                double v = S[r * 128 + c];
                if (c == k) v = 0.0;
                S[r * 128 + c] = v - f[m] * rk;
            }
        }
        __syncthreads();
    }
    for (int k = 127; k >= 0; k--) {
        int p = perm[k];
        if (p != k && tid < 128) {
            double t = S[tid * 128 + k];
            S[tid * 128 + k] = S[tid * 128 + p];
            S[tid * 128 + p] = t;
        }
        __syncthreads();
    }
    for (int idx = tid; idx < 16384; idx += 1024) {
        int o = idx >> 7, i = idx & 127;
        g_MT[(size_t)a * 16384 + idx] = (float)(S[i * 128 + o] + (i == o ? 1.0 : 0.0));
    }
}

// ---------------- CSR build ------------------------------------------------------
__device__ __forceinline__ void graph_ptrs(int g, const int* eia, const int* eif,
                                           const int** gi, const int** si) {
    if (g < 3)      { *gi = eia + (size_t)g * 2 * EE;            *si = eia + (size_t)g * 2 * EE + EE; }
    else if (g < 6) { *gi = eia + (size_t)(g - 3) * 2 * EE + EE; *si = eia + (size_t)(g - 3) * 2 * EE; }
    else            { *gi = eif + EFN;                           *si = eif; }
}

__global__ void hist_k(const int* __restrict__ eia, const int* __restrict__ eif) {
    int g = blockIdx.y;
    const int *gi, *si;
    graph_ptrs(g, eia, eif, &gi, &si);
    int e = blockIdx.x * blockDim.x + threadIdx.x;
    if (e < EE) atomicAdd(g_fill + (size_t)g * NN + si[e], 1);
}

// pass 1: per-block sums
__global__ __launch_bounds__(1024)
void scan_p1() {
    int g = blockIdx.y, b = blockIdx.x, tid = threadIdx.x;
    int i = b * 1024 + tid;
    int v = (i < NN) ? g_fill[(size_t)g * NN + i] : 0;
    #pragma unroll
    for (int o = 16; o; o >>= 1) v += __shfl_down_sync(~0u, v, o);
    __shared__ int w[32];
    if ((tid & 31) == 0) w[tid >> 5] = v;
    __syncthreads();
    if (tid < 32) {
        int x = w[tid];
        #pragma unroll
        for (int o = 16; o; o >>= 1) x += __shfl_down_sync(~0u, x, o);
        if (tid == 0) g_bsum[g * NBLK + b] = x;
    }
}
// pass 2: scan block sums (7 graphs, one lane each)
__global__ void scan_p2() {
    int wid = threadIdx.x >> 5, lane = threadIdx.x & 31;
    if (wid < 7 && lane == 0) {
        int run = 0;
        for (int j = 0; j < NBLK; j++) {
            int t = g_bsum[wid * NBLK + j];
            g_bsum[wid * NBLK + j] = run;
            run += t;
        }
        g_rowptr[(size_t)wid * (NN + 1) + NN] = run;
    }
}
// pass 3: block-local exclusive scan + base; writes rowptr and fill cursors
__global__ __launch_bounds__(1024)
void scan_p3() {
    int g = blockIdx.y, b = blockIdx.x, tid = threadIdx.x;
    int i = b * 1024 + tid;
    int v = (i < NN) ? g_fill[(size_t)g * NN + i] : 0;
    __shared__ int s[1024];
    s[tid] = v;
    __syncthreads();
    for (int off = 1; off < 1024; off <<= 1) {
        int t = (tid >= off) ? s[tid - off] : 0;
        __syncthreads();
        s[tid] += t;
        __syncthreads();
    }
    if (i < NN) {
        int val = g_bsum[g * NBLK + b] + s[tid] - v;
        g_rowptr[(size_t)g * (NN + 1) + i] = val;
        g_fill[(size_t)g * NN + i] = val;
    }
}

__global__ void fill_k(const int* __restrict__ eia, const int* __restrict__ eif) {
    int g = blockIdx.y;
    const int *gi, *si;
    graph_ptrs(g, eia, eif, &gi, &si);
    int e = blockIdx.x * blockDim.x + threadIdx.x;
    if (e < EE) {
        int pos = atomicAdd(g_fill + (size_t)g * NN + si[e], 1);
        g_eord[(size_t)g * EE + pos] = gi[e];
    }
}

// ---------------- gather-mean ----------------------------------------------------
__global__ __launch_bounds__(256)
void gather_mean(const float* __restrict__ data, long dataBStr,
                 int gbase, int fam4, float* __restrict__ outp, long outBStr) {
    int a = blockIdx.y;
    int g = (fam4 && a == 3) ? 6 : (gbase + a);
    const float* d = data + (size_t)a * dataBStr;
    float* o = outp + (size_t)a * outBStr;
    const int* rp = g_rowptr + (size_t)g * (NN + 1);
    const int* eo = g_eord + (size_t)g * EE;

    int node = blockIdx.x * 8 + (threadIdx.x >> 5);
    int lane = threadIdx.x & 31;
    if (node >= NN) return;
    int s = rp[node], e = rp[node + 1];
    float4 acc = make_float4(0.f, 0.f, 0.f, 0.f);
    int j = s;
    for (; j + 1 < e; j += 2) {
        int g0 = eo[j], g1 = eo[j + 1];
        float4 v0 = ((const float4*)(d + (size_t)g0 * DD))[lane];
        float4 v1 = ((const float4*)(d + (size_t)g1 * DD))[lane];
        acc.x += v0.x + v1.x; acc.y += v0.y + v1.y;
        acc.z += v0.z + v1.z; acc.w += v0.w + v1.w;
    }
    if (j < e) {
        float4 v = ((const float4*)(d + (size_t)eo[j] * DD))[lane];
        acc.x += v.x; acc.y += v.y; acc.z += v.z; acc.w += v.w;
    }
    float inv = 1.0f / fmaxf((float)(e - s), 1.0f);
    acc.x *= inv; acc.y *= inv; acc.z *= inv; acc.w *= inv;
    ((float4*)(o + (size_t)node * DD))[lane] = acc;
}

// ---------------- bf16 m16n8k16 fused GEMM, double-buffered ----------------------
// Out[row] = act( In1[row] @ W1^T + In2row @ W2^T + bias )
// GIN: In1 rows (and GOUT: Out rows) indirected via ridx. SEL2: In2 row r taken
// from In2b[sel2[r]-1] when sel2[r]>0 else In2[r]. In2 row pointers live in a
// shared table (sP2) so the mainloop carries no extra registers.
#define RSTR 20
static constexpr int STAGE_WORDS = 128 * RSTR;
static constexpr int GEMM_SMEM = 2048 + 2 * 4 * STAGE_WORDS * 4;   // 83968

template<bool HAS2, bool GIN, bool GOUT, bool RELU, bool HASBIAS, bool SEL2>
__global__ __launch_bounds__(512)
void gemm_tc(const float* __restrict__ In1, int in1Stride, long in1BStr,
             const float* __restrict__ W1, int w1Stride, long w1BStr,
             const float* __restrict__ In2, int in2Stride, long in2BStr,
             const float* __restrict__ In2b, long in2bBStr, const int* __restrict__ sel2,
             const float* __restrict__ W2, int w2Stride, long w2BStr,
             const float* __restrict__ bias, long biasBStr,
             const int*   __restrict__ ridx,
             float* __restrict__ Out, long outBStr, int nrows) {
    extern __shared__ __align__(16) char smem[];
    int*      sRow  = (int*)smem;                            // 512 B
    float*    sBias = (float*)(smem + 512);                  // 512 B
    unsigned long long* sP2 = (unsigned long long*)(smem + 1024);  // 1024 B
    uint32_t* sBase = (uint32_t*)(smem + 2048);

    {
        long a = blockIdx.y;
        In1 += a * in1BStr; W1 += a * w1BStr;
        if (HAS2) { In2 += a * in2BStr; W2 += a * w2BStr; }
        if (SEL2) In2b += a * in2bBStr;
        if (HASBIAS) bias += a * biasBStr;
        Out += a * outBStr;
    }

    int tid = threadIdx.x, wid = tid >> 5, lane = tid & 31;
    int g = lane >> 2, tg = lane & 3;
    int warpM = wid >> 2, warpN = wid & 3;
    int row0 = blockIdx.x * 128;

    if (tid < 128) {
        int gr = row0 + tid;
        int e = 0;
        if (gr < nrows) e = GIN ? ridx[gr] : gr;
        sRow[tid] = e;
        if (HASBIAS) sBias[tid] = bias[tid];
        if (HAS2) {
            int g2 = (gr < nrows) ? gr : (nrows - 1);
            const float* p;
            if (SEL2) {
                int s2 = sel2[g2];
                p = (s2 > 0) ? In2b + (size_t)(s2 - 1) * DD
                             : In2 + (size_t)g2 * in2Stride;
            } else {
                p = In2 + (size_t)g2 * in2Stride;
            }
            sP2[tid] = (unsigned long long)p;
        }
    }
    __syncthreads();

    float acc[2][4][4];
    #pragma unroll
    for (int mt = 0; mt < 2; mt++)
        #pragma unroll
        for (int nt = 0; nt < 4; nt++)
            #pragma unroll
            for (int i = 0; i < 4; i++) acc[mt][nt][i] = 0.0f;

    const int np = HAS2 ? 8 : 4;
    int frr = tid >> 2, fsg = (tid & 3) * 2;

    float4 rA[2], rB[2];

    auto ldg = [&](int p) {
        int op = HAS2 ? (p >> 2) : 0;
        int kc = (p & 3) * 32;
        const float* ap;
        if (op == 0) ap = In1 + (size_t)sRow[frr] * in1Stride;
        else         ap = (const float*)sP2[frr];
        const float* bw = (op == 0) ? W1 : W2;
        int bst = (op == 0) ? w1Stride : w2Stride;
        #pragma unroll
        for (int q = 0; q < 2; q++) {
            int seg = fsg + q;
            rA[q] = *(const float4*)(ap + kc + seg * 4);
            rB[q] = *(const float4*)(bw + (size_t)frr * bst + kc + seg * 4);
        }
    };
    auto sts = [&](int p) {
        uint32_t* st  = sBase + (p & 1) * (4 * STAGE_WORDS);
        uint32_t* tAh = st;
        uint32_t* tAl = st + STAGE_WORDS;
        uint32_t* tBh = st + 2 * STAGE_WORDS;
        uint32_t* tBl = st + 3 * STAGE_WORDS;
        #pragma unroll
        for (int q = 0; q < 2; q++) {
            int seg = fsg + q;
            int wa = frr * RSTR + seg * 2;
            uint32_t lo0, lo1;
            uint32_t hi0 = packsplit(rA[q].x, rA[q].y, lo0);
            uint32_t hi1 = packsplit(rA[q].z, rA[q].w, lo1);
            tAh[wa] = hi0; tAh[wa + 1] = hi1;
            tAl[wa] = lo0; tAl[wa + 1] = lo1;
            uint32_t wl0, wl1;
            uint32_t wh0 = packsplit(rB[q].x, rB[q].y, wl0);
            uint32_t wh1 = packsplit(rB[q].z, rB[q].w, wl1);
            tBh[wa] = wh0; tBh[wa + 1] = wh1;
            tBl[wa] = wl0; tBl[wa + 1] = wl1;
        }
    };

    ldg(0);
    sts(0);
    if (np > 1) ldg(1);
    __syncthreads();

    for (int p = 0; p < np; p++) {
        if (p + 1 < np) sts(p + 1);
        if (p + 2 < np) ldg(p + 2);
        uint32_t* st  = sBase + (p & 1) * (4 * STAGE_WORDS);
        uint32_t* sAhi = st;
        uint32_t* sAlo = st + STAGE_WORDS;
        uint32_t* sBhi = st + 2 * STAGE_WORDS;
        uint32_t* sBlo = st + 3 * STAGE_WORDS;
        #pragma unroll
        for (int ks = 0; ks < 2; ks++) {
            int wb = ks * 8 + tg;
            uint32_t aH[2][4], aL[2][4];
            #pragma unroll
            for (int mt = 0; mt < 2; mt++) {
                int rb = (warpM * 32 + mt * 16 + g) * RSTR;
                aH[mt][0] = sAhi[rb + wb];
                aH[mt][1] = sAhi[rb + 8 * RSTR + wb];
                aH[mt][2] = sAhi[rb + wb + 4];
                aH[mt][3] = sAhi[rb + 8 * RSTR + wb + 4];
                aL[mt][0] = sAlo[rb + wb];
                aL[mt][1] = sAlo[rb + 8 * RSTR + wb];
                aL[mt][2] = sAlo[rb + wb + 4];
                aL[mt][3] = sAlo[rb + 8 * RSTR + wb + 4];
            }
            #pragma unroll
            for (int nt = 0; nt < 4; nt++) {
                int nb = (warpN * 32 + nt * 8 + g) * RSTR;
                uint32_t bh0 = sBhi[nb + wb], bh1 = sBhi[nb + wb + 4];
                uint32_t bl0 = sBlo[nb + wb], bl1 = sBlo[nb + wb + 4];
                #pragma unroll
                for (int mt = 0; mt < 2; mt++) {
                    mma16(acc[mt][nt], aH[mt], bh0, bh1);
                    mma16(acc[mt][nt], aL[mt], bh0, bh1);
                    mma16(acc[mt][nt], aH[mt], bl0, bl1);
                }
            }
        }
        __syncthreads();
    }

    #pragma unroll
    for (int mt = 0; mt < 2; mt++) {
        #pragma unroll
        for (int half = 0; half < 2; half++) {
            int lr = warpM * 32 + mt * 16 + g + half * 8;
            int grow = row0 + lr;
            if (grow < nrows) {
                int orow = GOUT ? sRow[lr] : grow;
                float* ob = Out + (size_t)orow * 128;
                #pragma unroll
                for (int nt = 0; nt < 4; nt++) {
                    int col = warpN * 32 + nt * 8 + tg * 2;
                    float v0 = acc[mt][nt][half * 2 + 0];
                    float v1 = acc[mt][nt][half * 2 + 1];
                    if (HASBIAS) { v0 += sBias[col]; v1 += sBias[col + 1]; }
                    if (RELU) { v0 = fmaxf(v0, 0.0f); v1 = fmaxf(v1, 0.0f); }
                    float2 pp; pp.x = v0; pp.y = v1;
                    *(float2*)(ob + col) = pp;
                }
            }
        }
    }
}

// ---------------- host orchestration -------------------------------------------
extern "C" void kernel_launch(void* const* d_in, const int* in_sizes, int n_in,
                              void* d_out, int out_size) {
    int iXI, iXA, iPF, iPOP, iEIA, iEIF, iPROJ, iAGGW, iAGGB,
        iWL1, iBL1, iWR1, iWL2, iBL2, iWR2, iWL3, iBL3, iWR3;
    if (in_sizes[3] == PP) {  // setup_inputs dict order
        iXI = 0; iXA = 1; iPF = 2; iPOP = 3; iEIA = 4; iEIF = 5;
        iPROJ = 6; iAGGW = 7; iAGGB = 8; iWL1 = 9; iBL1 = 10; iWR1 = 11;
        iWL2 = 12; iBL2 = 13; iWR2 = 14; iWL3 = 15; iBL3 = 16; iWR3 = 17;
    } else {                  // reference() signature order
        iXI = 0; iXA = 1; iPF = 2; iPROJ = 3; iAGGW = 4; iAGGB = 5;
        iWL1 = 6; iBL1 = 7; iWR1 = 8; iWL2 = 9; iBL2 = 10; iWR2 = 11;
        iWL3 = 12; iBL3 = 13; iWR3 = 14; iPOP = 15; iEIA = 16; iEIF = 17;
    }

    const float* xi   = (const float*)d_in[iXI];
    const float* xa   = (const float*)d_in[iXA];
    const float* pf   = (const float*)d_in[iPF];
    const int*   pop  = (const int*)d_in[iPOP];
    const int*   eia  = (const int*)d_in[iEIA];
    const int*   eif  = (const int*)d_in[iEIF];
    const float* proj = (const float*)d_in[iPROJ];
    const float* aggW = (const float*)d_in[iAGGW];
    const float* aggB = (const float*)d_in[iAGGB];
    const float* wl1  = (const float*)d_in[iWL1];
    const float* bl1  = (const float*)d_in[iBL1];
    const float* wr1  = (const float*)d_in[iWR1];
    const float* wl2  = (const float*)d_in[iWL2];
    const float* bl2  = (const float*)d_in[iBL2];
    const float* wr2  = (const float*)d_in[iWR2];
    const float* wl3  = (const float*)d_in[iWL3];
    const float* bl3  = (const float*)d_in[iBL3];
    const float* wr3  = (const float*)d_in[iWR3];

    float* out = (float*)d_out;  // [x_ind_out (N*D)] then [x_att_out (A*N*D)]

    float *hbuf, *xatt_b, *agg, *esf, *projT, *MT;
    int *fillp, *ipop;
    cudaGetSymbolAddress((void**)&hbuf,   g_hbuf);
    cudaGetSymbolAddress((void**)&xatt_b, g_xatt_b);
    cudaGetSymbolAddress((void**)&agg,    g_agg);
    cudaGetSymbolAddress((void**)&esf,    g_esf);
    cudaGetSymbolAddress((void**)&projT,  g_projT);
    cudaGetSymbolAddress((void**)&MT,     g_MT);
    cudaGetSymbolAddress((void**)&fillp,  g_fill);
    cudaGetSymbolAddress((void**)&ipop,   g_ipop);
    float* agg3 = agg + 3 * ND;

    cudaFuncSetAttribute(inv_kernel, cudaFuncAttributeMaxDynamicSharedMemorySize, 131072);
    cudaFuncSetAttribute(gemm_tc<false, false, false, false, false, false>,
                         cudaFuncAttributeMaxDynamicSharedMemorySize, GEMM_SMEM);
    cudaFuncSetAttribute(gemm_tc<true, true, false, true, true, false>,
                         cudaFuncAttributeMaxDynamicSharedMemorySize, GEMM_SMEM);
    cudaFuncSetAttribute(gemm_tc<true, false, false, false, true, true>,
                         cudaFuncAttributeMaxDynamicSharedMemorySize, GEMM_SMEM);
    cudaFuncSetAttribute(gemm_tc<false, true, true, true, false, false>,
                         cudaFuncAttributeMaxDynamicSharedMemorySize, GEMM_SMEM);
    cudaFuncSetAttribute(gemm_tc<true, false, false, false, true, false>,
                         cudaFuncAttributeMaxDynamicSharedMemorySize, GEMM_SMEM);

    const int gP = (PP + 127) / 128;  // 391
    const int gN = (NN + 127) / 128;  // 782
    const int eB = (EE + 255) / 256;
    const int nB = (NN + 7) / 8;

    // --- prep: transpose, inverse, ipop ---
    transpose_wt<<<AA, 256>>>(projT, proj);
    inv_kernel<<<AA, 1024, 131072>>>(proj);
    cudaMemsetAsync(ipop, 0, (size_t)NN * sizeof(int), 0);
    ipop_k<<<(PP + 255) / 256, 256>>>(pop);

    // --- CSR build for all 7 graphs ---
    cudaMemsetAsync(fillp, 0, (size_t)7 * NN * sizeof(int), 0);
    hist_k<<<dim3(eB, 7), 256>>>(eia, eif);
    scan_p1<<<dim3(NBLK, 7), 1024>>>();
    scan_p2<<<1, 256>>>();
    scan_p3<<<dim3(NBLK, 7), 1024>>>();
    fill_k<<<dim3(eB, 7), 256>>>(eia, eif);

    // 3) esf[a] = PF[:,a,:] @ proj[a]   (tensor-core GEMM; B = projT [o][i])
    gemm_tc<false, false, false, false, false, false><<<dim3(gP, AA), 512, GEMM_SMEM>>>(
        pf, AA * DD, (long)DD, projT, 128, 16384,
        nullptr, 0, 0, nullptr, 0, nullptr,
        nullptr, 0, 0,
        nullptr, 0, nullptr,
        esf, (long)PD, PP);

    // 4) hbuf[a][i] = relu(xa[a][pop[i]] @ aggW1^T + esf[a][i] @ aggW2^T + aggB)
    gemm_tc<true, true, false, true, true, false><<<dim3(gP, AA), 512, GEMM_SMEM>>>(
        xa, DD, (long)ND, aggW, 256, 0,
        esf, DD, (long)PD, nullptr, 0, nullptr,
        aggW + 128, 256, 0,
        aggB, 0, pop,
        hbuf, (long)PD, PP);

    // 5+10) agg = seg-mean of xi: graphs 0-2 (dst-seg) and 6 (family)
    gather_mean<<<dim3(nB, 4), 256>>>(xi, 0, 0, 1, agg, (long)ND);

    // 6) x_att_b = agg @ W_l1^T + b_l1 + x_att_a @ W_r1^T  (x_att_a via hbuf/xa select)
    gemm_tc<true, false, false, false, true, true><<<dim3(gN, AA), 512, GEMM_SMEM>>>(
        agg, DD, (long)ND, wl1, 128, 16384,
        xa, DD, (long)ND, hbuf, (long)PD, ipop,
        wr1, 128, 16384,
        bl1, DD, nullptr,
        xatt_b, (long)ND, NN);

    // 7) population rows: x_att_b[pop] = relu(x_att_b[pop] @ (inv(proj)+I))
    gemm_tc<false, true, true, true, false, false><<<dim3(gP, AA), 512, GEMM_SMEM>>>(
        xatt_b, DD, (long)ND, MT, 128, 16384,
        nullptr, 0, 0, nullptr, 0, nullptr,
        nullptr, 0, 0,
        nullptr, 0, pop,
        xatt_b, (long)ND, PP);

    // 8) agg = seg-mean of x_att_b over src (graphs 3-5)
    gather_mean<<<dim3(nB, AA), 256>>>(xatt_b, (long)ND, 3, 0, agg, (long)ND);

    // 9) x_att_out = agg @ W_l2^T + b_l2 + x_att_b @ W_r2^T  -> d_out[N*D:]
    gemm_tc<true, false, false, false, true, false><<<dim3(gN, AA), 512, GEMM_SMEM>>>(
        agg, DD, (long)ND, wl2, 128, 16384,
        xatt_b, DD, (long)ND, nullptr, 0, nullptr,
        wr2, 128, 16384,
        bl2, DD, nullptr,
        out + ND, (long)ND, NN);

    // 11) x_ind_out = agg3 @ W_l3^T + b_l3 + xi @ W_r3^T -> d_out[0:]
    gemm_tc<true, false, false, false, true, false><<<dim3(gN, 1), 512, GEMM_SMEM>>>(
        agg3, DD, 0, wl3, 128, 0,
        xi, DD, 0, nullptr, 0, nullptr,
        wr3, 128, 0,
        bl3, 0, nullptr,
        out, 0, NN);
}

// round 15
// speedup vs baseline: 1.5603x; 1.0371x over previous
#include <cuda_runtime.h>
#include <cuda_bf16.h>
#include <cstdint>
#include <cstddef>

#define NN 100000
#define DD 128
#define AA 3
#define PP 50000
#define EE 500000
#define EFN 500000

#define ND  ((size_t)NN * DD)
#define PD  ((size_t)PP * DD)
#define NBLK 98   // (NN + 1023) / 1024

// ---------------- scratch (static device globals; no allocation) ----------------
__device__ float    g_hbuf  [AA * PP * DD];   // compact h rows (population)
__device__ float    g_xatt_b[AA * NN * DD];
__device__ float    g_agg   [4 * NN * DD];    // slots 0-2: attr agg; slot 3: family agg
__device__ float    g_fdummy[AA * 128 * 128]; // fold GEMM f32 out (unused)
__device__ int      g_ipop  [NN];             // node -> pop position+1 (0 = absent)
// pre-split weights: slot s = 16384 words; hi at [s*16384 + n*64 + w], lo at +8192.
// slots: 0 aggW1, 1-3 wl1, 4-6 wr1, 7-9 wl2, 10-12 wr2, 13 wl3, 14 wr3,
//        15-17 proj, 18-20 MT (inv), 21-23 C (fold)
__device__ __align__(16) uint32_t g_ws[24 * 16384];
// CSR structures for the 7 edge graphs (0-2: attr dst-seg, 3-5: attr src-seg, 6: family)
__device__ int    g_rowptr[7 * (NN + 1)];
__device__ int    g_fill  [7 * NN];
__device__ int    g_eord  [7 * EE];
__device__ int    g_bsum  [7 * NBLK];

// m16n8k16 bf16 mma (sm_80+ portable)
__device__ __forceinline__ void mma16(float* c, const uint32_t* a, uint32_t b0, uint32_t b1) {
    asm volatile("mma.sync.aligned.m16n8k16.row.col.f32.bf16.bf16.f32 "
                 "{%0,%1,%2,%3}, {%4,%5,%6,%7}, {%8,%9}, {%0,%1,%2,%3};"
                 : "+f"(c[0]), "+f"(c[1]), "+f"(c[2]), "+f"(c[3])
                 : "r"(a[0]), "r"(a[1]), "r"(a[2]), "r"(a[3]), "r"(b0), "r"(b1));
}
// split (x,y) into packed bf16x2 hi + lo
__device__ __forceinline__ uint32_t packsplit(float x, float y, uint32_t& lopack) {
    float hx = __bfloat162float(__float2bfloat16(x));
    float hy = __bfloat162float(__float2bfloat16(y));
    uint32_t hi;
    asm("cvt.rn.bf16x2.f32 %0, %1, %2;" : "=r"(hi) : "f"(hy), "f"(hx));
    asm("cvt.rn.bf16x2.f32 %0, %1, %2;" : "=r"(lopack) : "f"(y - hy), "f"(x - hx));
    return hi;
}

// ---------------- weight pre-split: f32 [n][k] -> bf16 hi/lo slot ---------------
__global__ __launch_bounds__(1024)
void wconv(const float* __restrict__ aggW, const float* __restrict__ wl1,
           const float* __restrict__ wr1, const float* __restrict__ wl2,
           const float* __restrict__ wr2, const float* __restrict__ wl3,
           const float* __restrict__ wr3, const float* __restrict__ proj) {
    int b = blockIdx.x;
    const float* src; int st;
    if (b == 0)       { src = aggW;                 st = 256; }
    else if (b < 4)   { src = wl1 + (b - 1) * 16384;  st = 128; }
    else if (b < 7)   { src = wr1 + (b - 4) * 16384;  st = 128; }
    else if (b < 10)  { src = wl2 + (b - 7) * 16384;  st = 128; }
    else if (b < 13)  { src = wr2 + (b - 10) * 16384; st = 128; }
    else if (b == 13) { src = wl3;                  st = 128; }
    else if (b == 14) { src = wr3;                  st = 128; }
    else              { src = proj + (b - 15) * 16384; st = 128; }
    uint32_t* dh = g_ws + (size_t)b * 16384;
    for (int idx = threadIdx.x; idx < 8192; idx += 1024) {
        int n = idx >> 6, w = idx & 63;
        float x = src[(size_t)n * st + 2 * w];
        float y = src[(size_t)n * st + 2 * w + 1];
        uint32_t lo;
        uint32_t hi = packsplit(x, y, lo);
        dh[n * 64 + w] = hi;
        dh[8192 + n * 64 + w] = lo;
    }
}

// ---------------- ipop: node -> population position + 1 -------------------------
__global__ void ipop_k(const int* __restrict__ pop) {
    int i = blockIdx.x * blockDim.x + threadIdx.x;
    if (i < PP) g_ipop[pop[i]] = i + 1;
}

// ---------------- fp64 in-place Gauss-Jordan inverse, all in SMEM ---------------
// Emits MT = (inv(proj)+I)^T directly in split format (slots 18-20).
__global__ __launch_bounds__(1024)
void inv_kernel(const float* __restrict__ proj) {
    extern __shared__ double S[];            // 128*128
    __shared__ double pv[128];
    __shared__ int    pi[128];
    __shared__ int    perm[128];

    int a = blockIdx.x;
    int tid = threadIdx.x;
    int c = tid & 127, r0 = (tid >> 7) << 4;

    for (int idx = tid; idx < 16384; idx += 1024)
        S[idx] = (double)proj[(size_t)a * 16384 + idx];
    __syncthreads();

    for (int k = 0; k < 128; k++) {
        if (tid < 128) {
            pv[tid] = (tid >= k) ? fabs(S[tid * 128 + k]) : -1.0;
            pi[tid] = tid;
        }
        __syncthreads();
        for (int s = 64; s > 0; s >>= 1) {
            if (tid < s && pv[tid + s] > pv[tid]) { pv[tid] = pv[tid + s]; pi[tid] = pi[tid + s]; }
            __syncthreads();
        }
        int piv = pi[0];
        if (tid == 0) perm[k] = piv;
        if (tid < 128) {
            double vk = S[k * 128 + tid];
            if (piv != k) {
                double vp = S[piv * 128 + tid];
                S[piv * 128 + tid] = vk;
                vk = vp;
            }
            pv[tid] = vk;
        }
        __syncthreads();
        double d = pv[k];
        if (tid < 128) {
            double nv = ((tid == k) ? 1.0 : pv[tid]) / d;
            S[k * 128 + tid] = nv;
            pv[tid] = nv;
        }
        __syncthreads();
        double rk = pv[c];
        double f[16];
        #pragma unroll
        for (int m = 0; m < 16; m++) {
            int r = r0 + m;
            f[m] = (r == k) ? 0.0 : S[r * 128 + k];
        }
        __syncthreads();
        #pragma unroll
        for (int m = 0; m < 16; m++) {
            int r = r0 + m;
            if (r != k) {
                double v = S[r * 128 + c];
                if (c == k) v = 0.0;
                S[r * 128 + c] = v - f[m] * rk;
            }
        }
        __syncthreads();
    }
    for (int k = 127; k >= 0; k--) {
        int p = perm[k];
        if (p != k && tid < 128) {
            double t = S[tid * 128 + k];
            S[tid * 128 + k] = S[tid * 128 + p];
            S[tid * 128 + p] = t;
        }
        __syncthreads();
    }
    // MT[o][i] = inv[i][o] + (i==o), pre-split to slot 18+a
    uint32_t* dh = g_ws + (size_t)(18 + a) * 16384;
    for (int idx = tid; idx < 8192; idx += 1024) {
        int o = idx >> 6, w = idx & 63;
        int i0 = 2 * w, i1 = 2 * w + 1;
        float v0 = (float)(S[i0 * 128 + o] + (i0 == o ? 1.0 : 0.0));
        float v1 = (float)(S[i1 * 128 + o] + (i1 == o ? 1.0 : 0.0));
        uint32_t lo;
        uint32_t hi = packsplit(v0, v1, lo);
        dh[o * 64 + w] = hi;
        dh[8192 + o * 64 + w] = lo;
    }
}

// ---------------- CSR build ------------------------------------------------------
__device__ __forceinline__ void graph_ptrs(int g, const int* eia, const int* eif,
                                           const int** gi, const int** si) {
    if (g < 3)      { *gi = eia + (size_t)g * 2 * EE;            *si = eia + (size_t)g * 2 * EE + EE; }
    else if (g < 6) { *gi = eia + (size_t)(g - 3) * 2 * EE + EE; *si = eia + (size_t)(g - 3) * 2 * EE; }
    else            { *gi = eif + EFN;                           *si = eif; }
}

__global__ void hist_k(const int* __restrict__ eia, const int* __restrict__ eif) {
    int g = blockIdx.y;
    const int *gi, *si;
    graph_ptrs(g, eia, eif, &gi, &si);
    int e = blockIdx.x * blockDim.x + threadIdx.x;
    if (e < EE) atomicAdd(g_fill + (size_t)g * NN + si[e], 1);
}

__global__ __launch_bounds__(1024)
void scan_p1() {
    int g = blockIdx.y, b = blockIdx.x, tid = threadIdx.x;
    int i = b * 1024 + tid;
    int v = (i < NN) ? g_fill[(size_t)g * NN + i] : 0;
    #pragma unroll
    for (int o = 16; o; o >>= 1) v += __shfl_down_sync(~0u, v, o);
    __shared__ int w[32];
    if ((tid & 31) == 0) w[tid >> 5] = v;
    __syncthreads();
    if (tid < 32) {
        int x = w[tid];
        #pragma unroll
        for (int o = 16; o; o >>= 1) x += __shfl_down_sync(~0u, x, o);
        if (tid == 0) g_bsum[g * NBLK + b] = x;
    }
}
__global__ void scan_p2() {
    int wid = threadIdx.x >> 5, lane = threadIdx.x & 31;
    if (wid < 7 && lane == 0) {
        int run = 0;
        for (int j = 0; j < NBLK; j++) {
            int t = g_bsum[wid * NBLK + j];
            g_bsum[wid * NBLK + j] = run;
            run += t;
        }
        g_rowptr[(size_t)wid * (NN + 1) + NN] = run;
    }
}
__global__ __launch_bounds__(1024)
void scan_p3() {
    int g = blockIdx.y, b = blockIdx.x, tid = threadIdx.x;
    int i = b * 1024 + tid;
    int v = (i < NN) ? g_fill[(size_t)g * NN + i] : 0;
    __shared__ int s[1024];
    s[tid] = v;
    __syncthreads();
    for (int off = 1; off < 1024; off <<= 1) {
        int t = (tid >= off) ? s[tid - off] : 0;
        __syncthreads();
        s[tid] += t;
        __syncthreads();
    }
    if (i < NN) {
        int val = g_bsum[g * NBLK + b] + s[tid] - v;
        g_rowptr[(size_t)g * (NN + 1) + i] = val;
        g_fill[(size_t)g * NN + i] = val;
    }
}

__global__ void fill_k(const int* __restrict__ eia, const int* __restrict__ eif) {
    int g = blockIdx.y;
    const int *gi, *si;
    graph_ptrs(g, eia, eif, &gi, &si);
    int e = blockIdx.x * blockDim.x + threadIdx.x;
    if (e < EE) {
        int pos = atomicAdd(g_fill + (size_t)g * NN + si[e], 1);
        g_eord[(size_t)g * EE + pos] = gi[e];
    }
}

// ---------------- gather-mean (x4 unroll for MLP) --------------------------------
__global__ __launch_bounds__(256)
void gather_mean(const float* __restrict__ data, long dataBStr,
                 int gbase, int fam4, float* __restrict__ outp, long outBStr) {
    int a = blockIdx.y;
    int g = (fam4 && a == 3) ? 6 : (gbase + a);
    const float* d = data + (size_t)a * dataBStr;
    float* o = outp + (size_t)a * outBStr;
    const int* rp = g_rowptr + (size_t)g * (NN + 1);
    const int* eo = g_eord + (size_t)g * EE;

    int node = blockIdx.x * 8 + (threadIdx.x >> 5);
    int lane = threadIdx.x & 31;
    if (node >= NN) return;
    int s = rp[node], e = rp[node + 1];
    float4 acc = make_float4(0.f, 0.f, 0.f, 0.f);
    int j = s;
    for (; j + 3 < e; j += 4) {
        int g0 = eo[j], g1 = eo[j + 1], g2 = eo[j + 2], g3 = eo[j + 3];
        float4 v0 = ((const float4*)(d + (size_t)g0 * DD))[lane];
        float4 v1 = ((const float4*)(d + (size_t)g1 * DD))[lane];
        float4 v2 = ((const float4*)(d + (size_t)g2 * DD))[lane];
        float4 v3 = ((const float4*)(d + (size_t)g3 * DD))[lane];
        acc.x += (v0.x + v1.x) + (v2.x + v3.x);
        acc.y += (v0.y + v1.y) + (v2.y + v3.y);
        acc.z += (v0.z + v1.z) + (v2.z + v3.z);
        acc.w += (v0.w + v1.w) + (v2.w + v3.w);
    }
    if (j + 1 < e) {
        int g0 = eo[j], g1 = eo[j + 1];
        float4 v0 = ((const float4*)(d + (size_t)g0 * DD))[lane];
        float4 v1 = ((const float4*)(d + (size_t)g1 * DD))[lane];
        acc.x += v0.x + v1.x; acc.y += v0.y + v1.y;
        acc.z += v0.z + v1.z; acc.w += v0.w + v1.w;
        j += 2;
    }
    if (j < e) {
        float4 v = ((const float4*)(d + (size_t)eo[j] * DD))[lane];
        acc.x += v.x; acc.y += v.y; acc.z += v.z; acc.w += v.w;
    }
    float inv = 1.0f / fmaxf((float)(e - s), 1.0f);
    acc.x *= inv; acc.y *= inv; acc.z *= inv; acc.w *= inv;
    ((float4*)(o + (size_t)node * DD))[lane] = acc;
}

// ---------------- bf16 m16n8k16 fused GEMM, double-buffered ----------------------
// Out[row] = act( In1[row] @ W1^T + In2row @ W2^T + bias )
// W operands pre-split (hi at [n*64+w], lo at +8192). GIN/GOUT row indirection via
// ridx; SEL2 selects In2 row from In2b[sel2-1] or In2; WSOUT additionally emits the
// output pre-split into a weight slot (for the fold).
#define RSTR 20
static constexpr int STAGE_WORDS = 128 * RSTR;
static constexpr int GEMM_SMEM = 2048 + 2 * 4 * STAGE_WORDS * 4;   // 83968

template<bool HAS2, bool GIN, bool GOUT, bool RELU, bool HASBIAS, bool SEL2, bool WSOUT>
__global__ __launch_bounds__(512)
void gemm_tc(const float* __restrict__ In1, int in1Stride, long in1BStr,
             const uint32_t* __restrict__ W1s, long w1BStr,
             const float* __restrict__ In2, int in2Stride, long in2BStr,
             const float* __restrict__ In2b, long in2bBStr, const int* __restrict__ sel2,
             const uint32_t* __restrict__ W2s, long w2BStr,
             const float* __restrict__ bias, long biasBStr,
             const int*   __restrict__ ridx,
             float* __restrict__ Out, long outBStr,
             uint32_t* __restrict__ wsOut, long wsBStr,
             int nrows) {
    extern __shared__ __align__(16) char smem[];
    int*      sRow  = (int*)smem;                            // 512 B
    float*    sBias = (float*)(smem + 512);                  // 512 B
    unsigned long long* sP2 = (unsigned long long*)(smem + 1024);  // 1024 B
    uint32_t* sBase = (uint32_t*)(smem + 2048);

    {
        long a = blockIdx.y;
        In1 += a * in1BStr; W1s += a * w1BStr;
        if (HAS2) { In2 += a * in2BStr; W2s += a * w2BStr; }
        if (SEL2) In2b += a * in2bBStr;
        if (HASBIAS) bias += a * biasBStr;
        if (WSOUT) wsOut += a * wsBStr;
        Out += a * outBStr;
    }

    int tid = threadIdx.x, wid = tid >> 5, lane = tid & 31;
    int g = lane >> 2, tg = lane & 3;
    int warpM = wid >> 2, warpN = wid & 3;
    int row0 = blockIdx.x * 128;

    if (tid < 128) {
        int gr = row0 + tid;
        int e = 0;
        if (gr < nrows) e = GIN ? ridx[gr] : gr;
        sRow[tid] = e;
        if (HASBIAS) sBias[tid] = bias[tid];
        if (HAS2) {
            int g2 = (gr < nrows) ? gr : (nrows - 1);
            const float* p;
            if (SEL2) {
                int s2 = sel2[g2];
                p = (s2 > 0) ? In2b + (size_t)(s2 - 1) * DD
                             : In2 + (size_t)g2 * in2Stride;
            } else {
                p = In2 + (size_t)g2 * in2Stride;
            }
            sP2[tid] = (unsigned long long)p;
        }
    }
    __syncthreads();

    float acc[2][4][4];
    #pragma unroll
    for (int mt = 0; mt < 2; mt++)
        #pragma unroll
        for (int nt = 0; nt < 4; nt++)
            #pragma unroll
            for (int i = 0; i < 4; i++) acc[mt][nt][i] = 0.0f;

    const int np = HAS2 ? 8 : 4;
    int frr = tid >> 2, fsg = (tid & 3) * 2;

    float4 rA[2];
    uint4 rBh, rBl;

    auto ldg = [&](int p) {
        int op = HAS2 ? (p >> 2) : 0;
        int kc = (p & 3) * 32;
        const float* ap;
        if (op == 0) ap = In1 + (size_t)sRow[frr] * in1Stride;
        else         ap = (const float*)sP2[frr];
        rA[0] = *(const float4*)(ap + kc + fsg * 4);
        rA[1] = *(const float4*)(ap + kc + fsg * 4 + 4);
        const uint32_t* ws = (op == 0) ? W1s : W2s;
        int wbase = frr * 64 + (p & 3) * 16 + fsg * 2;
        rBh = *(const uint4*)(ws + wbase);
        rBl = *(const uint4*)(ws + 8192 + wbase);
    };
    auto sts = [&](int p) {
        uint32_t* st  = sBase + (p & 1) * (4 * STAGE_WORDS);
        uint32_t* tAh = st;
        uint32_t* tAl = st + STAGE_WORDS;
        uint32_t* tBh = st + 2 * STAGE_WORDS;
        uint32_t* tBl = st + 3 * STAGE_WORDS;
        #pragma unroll
        for (int q = 0; q < 2; q++) {
            int seg = fsg + q;
            int wa = frr * RSTR + seg * 2;
            uint32_t lo0, lo1;
            uint32_t hi0 = packsplit(rA[q].x, rA[q].y, lo0);
            uint32_t hi1 = packsplit(rA[q].z, rA[q].w, lo1);
            tAh[wa] = hi0; tAh[wa + 1] = hi1;
            tAl[wa] = lo0; tAl[wa + 1] = lo1;
        }
        *(uint4*)&tBh[frr * RSTR + fsg * 2] = rBh;
        *(uint4*)&tBl[frr * RSTR + fsg * 2] = rBl;
    };

    ldg(0);
    sts(0);
    if (np > 1) ldg(1);
    __syncthreads();

    for (int p = 0; p < np; p++) {
        if (p + 1 < np) sts(p + 1);
        if (p + 2 < np) ldg(p + 2);
        uint32_t* st  = sBase + (p & 1) * (4 * STAGE_WORDS);
        uint32_t* sAhi = st;
        uint32_t* sAlo = st + STAGE_WORDS;
        uint32_t* sBhi = st + 2 * STAGE_WORDS;
        uint32_t* sBlo = st + 3 * STAGE_WORDS;
        #pragma unroll
        for (int ks = 0; ks < 2; ks++) {
            int wb = ks * 8 + tg;
            uint32_t aH[2][4], aL[2][4];
            #pragma unroll
            for (int mt = 0; mt < 2; mt++) {
                int rb = (warpM * 32 + mt * 16 + g) * RSTR;
                aH[mt][0] = sAhi[rb + wb];
                aH[mt][1] = sAhi[rb + 8 * RSTR + wb];
                aH[mt][2] = sAhi[rb + wb + 4];
                aH[mt][3] = sAhi[rb + 8 * RSTR + wb + 4];
                aL[mt][0] = sAlo[rb + wb];
                aL[mt][1] = sAlo[rb + 8 * RSTR + wb];
                aL[mt][2] = sAlo[rb + wb + 4];
                aL[mt][3] = sAlo[rb + 8 * RSTR + wb + 4];
            }
            #pragma unroll
            for (int nt = 0; nt < 4; nt++) {
                int nb = (warpN * 32 + nt * 8 + g) * RSTR;
                uint32_t bh0 = sBhi[nb + wb], bh1 = sBhi[nb + wb + 4];
                uint32_t bl0 = sBlo[nb + wb], bl1 = sBlo[nb + wb + 4];
                #pragma unroll
                for (int mt = 0; mt < 2; mt++) {
                    mma16(acc[mt][nt], aH[mt], bh0, bh1);
                    mma16(acc[mt][nt], aL[mt], bh0, bh1);
                    mma16(acc[mt][nt], aH[mt], bl0, bl1);
                }
            }
        }
        __syncthreads();
    }

    #pragma unroll
    for (int mt = 0; mt < 2; mt++) {
        #pragma unroll
        for (int half = 0; half < 2; half++) {
            int lr = warpM * 32 + mt * 16 + g + half * 8;
            int grow = row0 + lr;
            if (grow < nrows) {
                int orow = GOUT ? sRow[lr] : grow;
                float* ob = Out + (size_t)orow * 128;
                #pragma unroll
                for (int nt = 0; nt < 4; nt++) {
                    int col = warpN * 32 + nt * 8 + tg * 2;
                    float v0 = acc[mt][nt][half * 2 + 0];
                    float v1 = acc[mt][nt][half * 2 + 1];
                    if (HASBIAS) { v0 += sBias[col]; v1 += sBias[col + 1]; }
                    if (RELU) { v0 = fmaxf(v0, 0.0f); v1 = fmaxf(v1, 0.0f); }
                    float2 pp; pp.x = v0; pp.y = v1;
                    *(float2*)(ob + col) = pp;
                    if (WSOUT) {
                        uint32_t lo;
                        uint32_t hi = packsplit(v0, v1, lo);
                        wsOut[(size_t)orow * 64 + (col >> 1)] = hi;
                        wsOut[8192 + (size_t)orow * 64 + (col >> 1)] = lo;
                    }
                }
            }
        }
    }
}

// ---------------- host orchestration -------------------------------------------
extern "C" void kernel_launch(void* const* d_in, const int* in_sizes, int n_in,
                              void* d_out, int out_size) {
    int iXI, iXA, iPF, iPOP, iEIA, iEIF, iPROJ, iAGGW, iAGGB,
        iWL1, iBL1, iWR1, iWL2, iBL2, iWR2, iWL3, iBL3, iWR3;
    if (in_sizes[3] == PP) {  // setup_inputs dict order
        iXI = 0; iXA = 1; iPF = 2; iPOP = 3; iEIA = 4; iEIF = 5;
        iPROJ = 6; iAGGW = 7; iAGGB = 8; iWL1 = 9; iBL1 = 10; iWR1 = 11;
        iWL2 = 12; iBL2 = 13; iWR2 = 14; iWL3 = 15; iBL3 = 16; iWR3 = 17;
    } else {                  // reference() signature order
        iXI = 0; iXA = 1; iPF = 2; iPROJ = 3; iAGGW = 4; iAGGB = 5;
        iWL1 = 6; iBL1 = 7; iWR1 = 8; iWL2 = 9; iBL2 = 10; iWR2 = 11;
        iWL3 = 12; iBL3 = 13; iWR3 = 14; iPOP = 15; iEIA = 16; iEIF = 17;
    }

    const float* xi   = (const float*)d_in[iXI];
    const float* xa   = (const float*)d_in[iXA];
    const float* pf   = (const float*)d_in[iPF];
    const int*   pop  = (const int*)d_in[iPOP];
    const int*   eia  = (const int*)d_in[iEIA];
    const int*   eif  = (const int*)d_in[iEIF];
    const float* proj = (const float*)d_in[iPROJ];
    const float* aggW = (const float*)d_in[iAGGW];
    const float* aggB = (const float*)d_in[iAGGB];
    const float* wl1  = (const float*)d_in[iWL1];
    const float* bl1  = (const float*)d_in[iBL1];
    const float* wr1  = (const float*)d_in[iWR1];
    const float* wl2  = (const float*)d_in[iWL2];
    const float* bl2  = (const float*)d_in[iBL2];
    const float* wr2  = (const float*)d_in[iWR2];
    const float* wl3  = (const float*)d_in[iWL3];
    const float* bl3  = (const float*)d_in[iBL3];
    const float* wr3  = (const float*)d_in[iWR3];

    float* out = (float*)d_out;  // [x_ind_out (N*D)] then [x_att_out (A*N*D)]

    float *hbuf, *xatt_b, *agg, *fdummy;
    uint32_t* ws;
    int *fillp, *ipop;
    cudaGetSymbolAddress((void**)&hbuf,   g_hbuf);
    cudaGetSymbolAddress((void**)&xatt_b, g_xatt_b);
    cudaGetSymbolAddress((void**)&agg,    g_agg);
    cudaGetSymbolAddress((void**)&fdummy, g_fdummy);
    cudaGetSymbolAddress((void**)&ws,     g_ws);
    cudaGetSymbolAddress((void**)&fillp,  g_fill);
    cudaGetSymbolAddress((void**)&ipop,   g_ipop);
    float* agg3 = agg + 3 * ND;

    cudaFuncSetAttribute(inv_kernel, cudaFuncAttributeMaxDynamicSharedMemorySize, 131072);
    cudaFuncSetAttribute(gemm_tc<false, false, false, false, false, false, true>,
                         cudaFuncAttributeMaxDynamicSharedMemorySize, GEMM_SMEM);
    cudaFuncSetAttribute(gemm_tc<true, true, false, true, true, false, false>,
                         cudaFuncAttributeMaxDynamicSharedMemorySize, GEMM_SMEM);
    cudaFuncSetAttribute(gemm_tc<true, false, false, false, true, true, false>,
                         cudaFuncAttributeMaxDynamicSharedMemorySize, GEMM_SMEM);
    cudaFuncSetAttribute(gemm_tc<false, true, true, true, false, false, false>,
                         cudaFuncAttributeMaxDynamicSharedMemorySize, GEMM_SMEM);
    cudaFuncSetAttribute(gemm_tc<true, false, false, false, true, false, false>,
                         cudaFuncAttributeMaxDynamicSharedMemorySize, GEMM_SMEM);

    const int gP = (PP + 127) / 128;  // 391
    const int gN = (NN + 127) / 128;  // 782
    const int eB = (EE + 255) / 256;
    const int nB = (NN + 7) / 8;

    // --- prep: weight pre-split, inverse (emits MT slots), ipop ---
    wconv<<<18, 1024>>>(aggW, wl1, wr1, wl2, wr2, wl3, wr3, proj);
    inv_kernel<<<AA, 1024, 131072>>>(proj);
    cudaMemsetAsync(ipop, 0, (size_t)NN * sizeof(int), 0);
    ipop_k<<<(PP + 255) / 256, 256>>>(pop);

    // --- CSR build for all 7 graphs ---
    cudaMemsetAsync(fillp, 0, (size_t)7 * NN * sizeof(int), 0);
    hist_k<<<dim3(eB, 7), 256>>>(eia, eif);
    scan_p1<<<dim3(NBLK, 7), 1024>>>();
    scan_p2<<<1, 256>>>();
    scan_p3<<<dim3(NBLK, 7), 1024>>>();
    fill_k<<<dim3(eB, 7), 256>>>(eia, eif);

    // fold: C[a] = aggW2 @ proj[a]^T  -> split slots 21-23 (tensor core, 3 blocks)
    gemm_tc<false, false, false, false, false, false, true><<<dim3(1, AA), 512, GEMM_SMEM>>>(
        aggW + 128, 256, 0,
        ws + (size_t)15 * 16384, 16384,
        nullptr, 0, 0, nullptr, 0, nullptr,
        nullptr, 0,
        nullptr, 0, nullptr,
        fdummy, 16384,
        ws + (size_t)21 * 16384, 16384,
        128);

    // 4) hbuf[a][i] = relu(xa[a][pop[i]] @ aggW1^T + pf[i,a,:] @ C[a]^T + aggB)
    gemm_tc<true, true, false, true, true, false, false><<<dim3(gP, AA), 512, GEMM_SMEM>>>(
        xa, DD, (long)ND,
        ws, 0,
        pf, AA * DD, (long)DD, nullptr, 0, nullptr,
        ws + (size_t)21 * 16384, 16384,
        aggB, 0, pop,
        hbuf, (long)PD,
        nullptr, 0,
        PP);

    // 5+10) agg = seg-mean of xi: graphs 0-2 (dst-seg) and 6 (family)
    gather_mean<<<dim3(nB, 4), 256>>>(xi, 0, 0, 1, agg, (long)ND);

    // 6) x_att_b = agg @ W_l1^T + b_l1 + x_att_a @ W_r1^T  (x_att_a via hbuf/xa select)
    gemm_tc<true, false, false, false, true, true, false><<<dim3(gN, AA), 512, GEMM_SMEM>>>(
        agg, DD, (long)ND,
        ws + (size_t)1 * 16384, 16384,
        xa, DD, (long)ND, hbuf, (long)PD, ipop,
        ws + (size_t)4 * 16384, 16384,
        bl1, DD, nullptr,
        xatt_b, (long)ND,
        nullptr, 0,
        NN);

    // 7) population rows: x_att_b[pop] = relu(x_att_b[pop] @ (inv(proj)+I))
    gemm_tc<false, true, true, true, false, false, false><<<dim3(gP, AA), 512, GEMM_SMEM>>>(
        xatt_b, DD, (long)ND,
        ws + (size_t)18 * 16384, 16384,
        nullptr, 0, 0, nullptr, 0, nullptr,
        nullptr, 0,
        nullptr, 0, pop,
        xatt_b, (long)ND,
        nullptr, 0,
        PP);

    // 8) agg = seg-mean of x_att_b over src (graphs 3-5)
    gather_mean<<<dim3(nB, AA), 256>>>(xatt_b, (long)ND, 3, 0, agg, (long)ND);

    // 9) x_att_out = agg @ W_l2^T + b_l2 + x_att_b @ W_r2^T  -> d_out[N*D:]
    gemm_tc<true, false, false, false, true, false, false><<<dim3(gN, AA), 512, GEMM_SMEM>>>(
        agg, DD, (long)ND,
        ws + (size_t)7 * 16384, 16384,
        xatt_b, DD, (long)ND, nullptr, 0, nullptr,
        ws + (size_t)10 * 16384, 16384,
        bl2, DD, nullptr,
        out + ND, (long)ND,
        nullptr, 0,
        NN);

    // 11) x_ind_out = agg3 @ W_l3^T + b_l3 + xi @ W_r3^T -> d_out[0:]
    gemm_tc<true, false, false, false, true, false, false><<<dim3(gN, 1), 512, GEMM_SMEM>>>(
        agg3, DD, 0,
        ws + (size_t)13 * 16384, 0,
        xi, DD, 0, nullptr, 0, nullptr,
        ws + (size_t)14 * 16384, 0,
        bl3, 0, nullptr,
        out, 0,
        nullptr, 0,
        NN);
}